// round 8
// baseline (speedup 1.0000x reference)
#include <cuda_runtime.h>
#include <cuda_fp16.h>
#include <math.h>
#include <stdint.h>

#define BATCH 512
#define TSEQ  256
#define DIN   128
#define HID   256
#define G4    1024
#define FDIM  64
#define EDIM  320
#define DM    384
#define NMERG 394
#define NL1   512
#define NACT  8

#define NBLK   128   // persistent grid: 16 col-tiles x 8 block-rows (2 groups each)
#define NGRP   16    // blocks per batch-group barrier

// ---------------- scratch (static device memory; no allocations) ----------------
__device__ __half d_xw[134217728];     // [T, B, 4H] fp16 pre-activations (permuted gates)
__device__ __half d_hs[33554432];      // [B, T, H] fp16 hidden states
__device__ __half d_hbuf[2 * BATCH * HID]; // double-buffered compact h (fp16)
__device__ int   d_bar[16 * TSEQ];     // per (batch-group, step) barrier counters
__device__ float d_Wip[G4 * DIN];      // permuted W_ih
__device__ float d_Wp[G4 * HID];       // permuted W_hh
__device__ float d_bp[G4];             // permuted bias
__device__ float d_sf[BATCH * EDIM];   // state_full
__device__ float d_q[BATCH * EDIM];
__device__ float d_qk[BATCH * HID];
__device__ float d_Mkp[EDIM * HID];    // Wk @ proj_W
__device__ float d_MA1[EDIM * HID];    // Wv @ proj_W
__device__ float d_Amat[EDIM * HID];   // Wo @ Wv @ proj_W
__device__ float d_vconst[EDIM];
__device__ float d_aconst[EDIM];
__device__ float d_hbar[BATCH * HID];
__device__ float d_ao[BATCH * EDIM];
__device__ float d_ms[BATCH * DM];
__device__ float d_qfeat[BATCH * 10];
__device__ float d_merged[BATCH * NMERG];
__device__ float d_x1[BATCH * NL1];

// ---------------- fp16 mma helpers ----------------
__device__ __forceinline__ uint32_t pack_h2(float x, float y) {
    __half2 t = __floats2half2_rn(x, y);
    return *reinterpret_cast<uint32_t*>(&t);
}
__device__ __forceinline__ void mma_f16(float* c, uint32_t a0, uint32_t a1,
                                        uint32_t a2, uint32_t a3,
                                        uint32_t b0, uint32_t b1) {
    asm volatile("mma.sync.aligned.m16n8k16.row.col.f32.f16.f16.f32 "
        "{%0,%1,%2,%3}, {%4,%5,%6,%7}, {%8,%9}, {%0,%1,%2,%3};"
        : "+f"(c[0]), "+f"(c[1]), "+f"(c[2]), "+f"(c[3])
        : "r"(a0), "r"(a1), "r"(a2), "r"(a3), "r"(b0), "r"(b1));
}
__device__ __forceinline__ float fsig(float x) {
    return __fdividef(1.f, 1.f + __expf(-x));
}
__device__ __forceinline__ float ftanh(float x) {
    return 2.f * fsig(2.f * x) - 1.f;
}

// ---------------- weight permutation: column 4u+g = gate g of unit u ----------------
__global__ void permute_kernel(const float* __restrict__ W_ih, const float* __restrict__ W_hh,
                               const float* __restrict__ b_ih, const float* __restrict__ b_hh,
                               float* __restrict__ Wip, float* __restrict__ Wp, float* __restrict__ bp) {
    int n = blockIdx.x;            // 0..1023, permuted row
    int u = n >> 2, g = n & 3;
    int o = g * HID + u;           // original row
    for (int k = threadIdx.x; k < DIN; k += blockDim.x) Wip[n * DIN + k] = W_ih[o * DIN + k];
    for (int k = threadIdx.x; k < HID; k += blockDim.x) Wp[n * HID + k] = W_hh[o * HID + k];
    if (threadIdx.x == 0) bp[n] = b_ih[o] + b_hh[o];
}

// ---------------- big input GEMM (fp16 mma): xw[t,b,:] = X[b,t,:] @ Wip^T + bp -------
__global__ __launch_bounds__(256) void xw_gemm_f16(
    const float* __restrict__ X, const float* __restrict__ Wip,
    const float* __restrict__ bp, __half* __restrict__ xw) {
    __shared__ __half sA[128][72];
    __shared__ __half sB[128][72];
    int m0 = blockIdx.y * 128;
    int n0 = blockIdx.x * 128;
    int tid = threadIdx.x;
    int wid = tid >> 5, lane = tid & 31;
    int g = lane >> 2, t4 = lane & 3;
    int warp_m = (wid & 1) * 64;
    int warp_n = (wid >> 1) * 32;

    float c[4][4][4];
    #pragma unroll
    for (int i = 0; i < 4; i++)
        #pragma unroll
        for (int j = 0; j < 4; j++)
            #pragma unroll
            for (int e = 0; e < 4; e++) c[i][j][e] = 0.f;

    for (int k0 = 0; k0 < DIN; k0 += 64) {
        #pragma unroll
        for (int it = 0; it < 8; it++) {
            int gi = it * 256 + tid;
            int row = gi >> 4;
            int c4 = gi & 15;
            {
                float4 v = __ldg((const float4*)(X + (size_t)(m0 + row) * DIN + k0 + c4 * 4));
                uint2 pk = { pack_h2(v.x, v.y), pack_h2(v.z, v.w) };
                *(uint2*)&sA[row][c4 * 4] = pk;
            }
            {
                float4 v = __ldg((const float4*)(Wip + (size_t)(n0 + row) * DIN + k0 + c4 * 4));
                uint2 pk = { pack_h2(v.x, v.y), pack_h2(v.z, v.w) };
                *(uint2*)&sB[row][c4 * 4] = pk;
            }
        }
        __syncthreads();
        #pragma unroll
        for (int kk = 0; kk < 4; kk++) {
            uint32_t br[4][2];
            #pragma unroll
            for (int j = 0; j < 4; j++) {
                const __half* bsrc = &sB[warp_n + 8 * j + g][kk * 16 + 2 * t4];
                br[j][0] = *(const uint32_t*)bsrc;
                br[j][1] = *(const uint32_t*)(bsrc + 8);
            }
            #pragma unroll
            for (int i = 0; i < 4; i++) {
                int r0 = warp_m + 16 * i + g;
                const __half* alo = &sA[r0][kk * 16 + 2 * t4];
                const __half* ahi = &sA[r0 + 8][kk * 16 + 2 * t4];
                uint32_t a0 = *(const uint32_t*)alo;
                uint32_t a2 = *(const uint32_t*)(alo + 8);
                uint32_t a1 = *(const uint32_t*)ahi;
                uint32_t a3 = *(const uint32_t*)(ahi + 8);
                #pragma unroll
                for (int j = 0; j < 4; j++)
                    mma_f16(c[i][j], a0, a1, a2, a3, br[j][0], br[j][1]);
            }
        }
        __syncthreads();
    }

    float2 bb[4];
    #pragma unroll
    for (int j = 0; j < 4; j++) {
        int col = n0 + warp_n + 8 * j + 2 * t4;
        bb[j].x = __ldg(bp + col); bb[j].y = __ldg(bp + col + 1);
    }
    #pragma unroll
    for (int i = 0; i < 4; i++) {
        int rlo = m0 + warp_m + 16 * i + g;
        int rhi = rlo + 8;
        __half* dlo = xw + ((size_t)(rlo & 255) * BATCH + (rlo >> 8)) * G4;
        __half* dhi = xw + ((size_t)(rhi & 255) * BATCH + (rhi >> 8)) * G4;
        #pragma unroll
        for (int j = 0; j < 4; j++) {
            int col = n0 + warp_n + 8 * j + 2 * t4;
            __half2 vlo = __floats2half2_rn(c[i][j][0] + bb[j].x, c[i][j][1] + bb[j].y);
            __half2 vhi = __floats2half2_rn(c[i][j][2] + bb[j].x, c[i][j][3] + bb[j].y);
            *(__half2*)(dlo + col) = vlo;
            *(__half2*)(dhi + col) = vhi;
        }
    }
}

// ---------------- persistent LSTM recurrence: dual-group interleaved fp16 mma --------
// 128 blocks: bx = col tile (64 gate cols), by = block-row. Each block services TWO
// independent batch groups (A = by, B = by+8; 32 batch rows each), alternating per
// step so each group's barrier latency hides behind the other group's compute.
__global__ __launch_bounds__(256, 1) void lstm_persist(
    const __half* __restrict__ xw, const float* __restrict__ Wp,
    __half* __restrict__ hs, __half* __restrict__ hbuf, int* __restrict__ bar)
{
    __shared__ __half sA[2][32][264];
    int bx = blockIdx.x & 15;       // col tile
    int by = blockIdx.x >> 4;       // block row (0..7)
    int n0 = bx * 64;
    int m0g[2] = { by * 32, (by + 8) * 32 };
    int tid = threadIdx.x;
    int wid = tid >> 5, lane = tid & 31;
    int g = lane >> 2, t4 = lane & 3;
    int warp_m = (wid & 1) * 16;
    int warp_n = (wid >> 1) * 16;
    int odd = lane & 1;

    // ---- preload B fragments (Wp^T, col-major k16 x n8), shared by both groups ----
    uint32_t breg[2][16][2];
    #pragma unroll
    for (int j = 0; j < 2; j++) {
        int col = n0 + warp_n + 8 * j + g;
        const float* wrow = Wp + (size_t)col * HID;
        #pragma unroll
        for (int kk = 0; kk < 16; kk++) {
            breg[j][kk][0] = pack_h2(__ldg(wrow + kk * 16 + 2 * t4),
                                     __ldg(wrow + kk * 16 + 2 * t4 + 1));
            breg[j][kk][1] = pack_h2(__ldg(wrow + kk * 16 + 2 * t4 + 8),
                                     __ldg(wrow + kk * 16 + 2 * t4 + 9));
        }
    }
    float creg[2][2] = { {0.f, 0.f}, {0.f, 0.f} };
    volatile int* vbar = bar;

    int rit = warp_m + g + (odd ? 8 : 0);              // row within 32-row tile
    int eu = ((n0 + warp_n) >> 2) + ((lane >> 1) & 1); // unit base

    for (int t = 0; t < TSEQ; t++) {
        #pragma unroll
        for (int grp = 0; grp < 2; grp++) {
            int gid = grp * 8 + by;
            float c[2][4];
            #pragma unroll
            for (int j = 0; j < 2; j++)
                #pragma unroll
                for (int e = 0; e < 4; e++) c[j][e] = 0.f;

            if (t > 0) {
                // wait for this group's previous step (arrived one phase ago)
                if (tid == 0) {
                    int bi = gid * TSEQ + (t - 1);
                    while (vbar[bi] < NGRP) {}
                }
                __syncthreads();
                // fill: 32 rows x 256 halves = 16 KB, one uint4 per thread x 4 iters
                const __half* hp = hbuf + (size_t)(t & 1) * (BATCH * HID);
                #pragma unroll
                for (int itr = 0; itr < 4; itr++) {
                    int gi = itr * 256 + tid;
                    int row = gi >> 5;
                    int s2 = gi & 31;
                    uint4 v = __ldcg((const uint4*)(hp + (size_t)(m0g[grp] + row) * HID + s2 * 8));
                    *(uint4*)&sA[grp][row][s2 * 8] = v;
                }
                __syncthreads();
                #pragma unroll
                for (int kk = 0; kk < 16; kk++) {
                    int r0 = warp_m + g;
                    const __half* alo = &sA[grp][r0 - warp_m + warp_m][kk * 16 + 2 * t4];
                    const __half* ahi = &sA[grp][r0 + 8][kk * 16 + 2 * t4];
                    uint32_t a0 = *(const uint32_t*)&sA[grp][r0][kk * 16 + 2 * t4];
                    uint32_t a2 = *(const uint32_t*)(&sA[grp][r0][kk * 16 + 2 * t4] + 8);
                    uint32_t a1 = *(const uint32_t*)ahi;
                    uint32_t a3 = *(const uint32_t*)(ahi + 8);
                    (void)alo;
                    mma_f16(c[0], a0, a1, a2, a3, breg[0][kk][0], breg[0][kk][1]);
                    mma_f16(c[1], a0, a1, a2, a3, breg[1][kk][0], breg[1][kk][1]);
                }
            }

            // ---- epilogue: gate exchange via shfl, cell update ----
            const __half* xwt = xw + (size_t)t * BATCH * G4;
            __half* hn = hbuf + (size_t)((t + 1) & 1) * (BATCH * HID);
            int brow = m0g[grp] + rit;
            float hvreg[2];
            #pragma unroll
            for (int j = 0; j < 2; j++) {
                float u0 = odd ? c[j][0] : c[j][2];
                float u1 = odd ? c[j][1] : c[j][3];
                float rx0 = __shfl_xor_sync(0xffffffffu, u0, 1);
                float rx1 = __shfl_xor_sync(0xffffffffu, u1, 1);
                float gi, gf, gg, go;
                if (!odd) { gi = c[j][0]; gf = c[j][1]; gg = rx0; go = rx1; }
                else      { gi = rx0; gf = rx1; gg = c[j][2]; go = c[j][3]; }
                int u = eu + 2 * j;
                uint2 raw = *(const uint2*)(xwt + (size_t)brow * G4 + 4 * u);
                float2 f01 = __half22float2(*reinterpret_cast<__half2*>(&raw.x));
                float2 f23 = __half22float2(*reinterpret_cast<__half2*>(&raw.y));
                gi += f01.x; gf += f01.y; gg += f23.x; go += f23.y;
                float i_ = fsig(gi);
                float f_ = fsig(gf);
                float g_ = ftanh(gg);
                float o_ = fsig(go);
                float cn = f_ * creg[grp][j] + i_ * g_;
                creg[grp][j] = cn;
                float hv = o_ * ftanh(cn);
                hvreg[j] = hv;
                hn[(size_t)brow * HID + u] = __float2half_rn(hv);
            }

            // arrive ASAP, then archive hs while peers arrive
            if (t < TSEQ - 1) {
                __threadfence();
                __syncthreads();
                if (tid == 0) atomicAdd(&bar[gid * TSEQ + t], 1);
            }
            #pragma unroll
            for (int j = 0; j < 2; j++)
                hs[((size_t)brow * TSEQ + t) * HID + eu + 2 * j] = __float2half_rn(hvreg[j]);
        }
    }
}

// ---------------- medium GEMM: C = A @ op(W) + bias, opt relu ------------------------
template <bool TRANS, bool RELU>
__global__ __launch_bounds__(256) void gemm_med(
    const float* __restrict__ A, const float* __restrict__ W,
    const float* __restrict__ bias, float* __restrict__ C,
    int M, int N, int K, int lda, int ldw, int ldc) {
    __shared__ float sA[16][68];
    __shared__ float sW[16][68];
    int m0 = blockIdx.y * 64, n0 = blockIdx.x * 64;
    int tid = threadIdx.x;
    int tx = tid & 15, ty = tid >> 4;
    float acc[4][4] = {};
    for (int k0 = 0; k0 < K; k0 += 16) {
        #pragma unroll
        for (int i = 0; i < 4; i++) {
            int idx = tid + i * 256;
            int r = idx >> 4, k = idx & 15;
            int mm = m0 + r, kk = k0 + k;
            sA[k][r] = (mm < M && kk < K) ? A[(size_t)mm * lda + kk] : 0.f;
            int nn = n0 + r;
            float v = 0.f;
            if (TRANS) { if (kk < K && nn < N) v = W[(size_t)kk * ldw + nn]; }
            else       { if (nn < N && kk < K) v = W[(size_t)nn * ldw + kk]; }
            sW[k][r] = v;
        }
        __syncthreads();
        #pragma unroll
        for (int k = 0; k < 16; k++) {
            float4 a = *(const float4*)&sA[k][ty * 4];
            float4 b = *(const float4*)&sW[k][tx * 4];
            acc[0][0] += a.x * b.x; acc[0][1] += a.x * b.y; acc[0][2] += a.x * b.z; acc[0][3] += a.x * b.w;
            acc[1][0] += a.y * b.x; acc[1][1] += a.y * b.y; acc[1][2] += a.y * b.z; acc[1][3] += a.y * b.w;
            acc[2][0] += a.z * b.x; acc[2][1] += a.z * b.y; acc[2][2] += a.z * b.z; acc[2][3] += a.z * b.w;
            acc[3][0] += a.w * b.x; acc[3][1] += a.w * b.y; acc[3][2] += a.w * b.z; acc[3][3] += a.w * b.w;
        }
        __syncthreads();
    }
    #pragma unroll
    for (int r = 0; r < 4; r++) {
        int m = m0 + ty * 4 + r;
        if (m >= M) continue;
        #pragma unroll
        for (int cc = 0; cc < 4; cc++) {
            int n = n0 + tx * 4 + cc;
            if (n >= N) continue;
            float v = acc[r][cc];
            if (bias) v += bias[n];
            if (RELU) v = fmaxf(v, 0.f);
            C[(size_t)m * ldc + n] = v;
        }
    }
}

// ---------------- tiny matvec ----------------
__global__ void matvec(const float* __restrict__ W, const float* __restrict__ x,
                       const float* __restrict__ bias, float* __restrict__ y,
                       int N, int K, int ldw) {
    int i = blockIdx.x * blockDim.x + threadIdx.x;
    if (i >= N) return;
    float a = bias ? bias[i] : 0.f;
    for (int k = 0; k < K; k++) a += W[(size_t)i * ldw + k] * x[k];
    y[i] = a;
}

// ---------------- fused attention over fp16 hs ---------------------------------------
__global__ void attn_kernel(const __half* __restrict__ hs, const float* __restrict__ qk,
                            float* __restrict__ hbar) {
    int b = blockIdx.x;
    __shared__ float sc[TSEQ];
    __shared__ float red[256];
    __shared__ float sqk[HID];
    int tid = threadIdx.x;
    int lane = tid & 31, w = tid >> 5;
    sqk[tid] = qk[b * HID + tid];
    __syncthreads();
    for (int t = w; t < TSEQ; t += 8) {
        const __half2* hrow = (const __half2*)(hs + ((size_t)b * TSEQ + t) * HID);
        float p = 0.f;
        #pragma unroll
        for (int j = 0; j < 4; j++) {
            int h2i = lane + 32 * j;
            float2 hv = __half22float2(hrow[h2i]);
            p += hv.x * sqk[2 * h2i] + hv.y * sqk[2 * h2i + 1];
        }
        #pragma unroll
        for (int o = 16; o > 0; o >>= 1) p += __shfl_down_sync(0xffffffffu, p, o);
        if (lane == 0) sc[t] = p;
    }
    __syncthreads();
    float scale = 1.0f / sqrtf((float)EDIM);
    float v = sc[tid] * scale;
    red[tid] = v; __syncthreads();
    for (int s = 128; s > 0; s >>= 1) { if (tid < s) red[tid] = fmaxf(red[tid], red[tid + s]); __syncthreads(); }
    float mx = red[0]; __syncthreads();
    float ev = expf(v - mx);
    red[tid] = ev; __syncthreads();
    for (int s = 128; s > 0; s >>= 1) { if (tid < s) red[tid] += red[tid + s]; __syncthreads(); }
    float sum = red[0]; __syncthreads();
    sc[tid] = ev / sum;
    __syncthreads();
    const __half* hb = hs + (size_t)b * TSEQ * HID;
    float acc = 0.f;
    for (int t = 0; t < TSEQ; t++) acc += sc[t] * __half2float(hb[(size_t)t * HID + tid]);
    hbar[b * HID + tid] = acc;
}

// ---------------- concat helpers ----------------
__global__ void sf_build(const __half* __restrict__ hs, const float* __restrict__ s,
                         float* __restrict__ sf) {
    int idx = blockIdx.x * blockDim.x + threadIdx.x;
    if (idx >= BATCH * EDIM) return;
    int b = idx / EDIM, j = idx % EDIM;
    sf[idx] = (j < HID) ? __half2float(hs[((size_t)b * TSEQ + (TSEQ - 1)) * HID + j])
                        : s[b * FDIM + (j - HID)];
}
__global__ void ms_build(const float* __restrict__ ao, const float* __restrict__ s,
                         float* __restrict__ ms) {
    int idx = blockIdx.x * blockDim.x + threadIdx.x;
    if (idx >= BATCH * DM) return;
    int b = idx / DM, j = idx % DM;
    ms[idx] = (j < EDIM) ? ao[b * EDIM + j] : s[b * FDIM + (j - EDIM)];
}
__global__ void merged_build(const float* __restrict__ ms, const float* __restrict__ qf,
                             float* __restrict__ mg) {
    int idx = blockIdx.x * blockDim.x + threadIdx.x;
    if (idx >= BATCH * NMERG) return;
    int b = idx / NMERG, j = idx % NMERG;
    mg[idx] = (j < DM) ? ms[b * DM + j] : qf[b * 10 + (j - DM)];
}

// ---------------- 10-qubit VQC, one block per batch element --------------------------
struct c2f { float x, y; };
__device__ __forceinline__ c2f cmul(c2f a, c2f b) { return { a.x * b.x - a.y * b.y, a.x * b.y + a.y * b.x }; }
__device__ __forceinline__ c2f cadd(c2f a, c2f b) { return { a.x + b.x, a.y + b.y }; }
__device__ __forceinline__ void matmul2(c2f C[2][2], const c2f A[2][2], const c2f B[2][2]) {
    #pragma unroll
    for (int i = 0; i < 2; i++)
        #pragma unroll
        for (int j = 0; j < 2; j++)
            C[i][j] = cadd(cmul(A[i][0], B[0][j]), cmul(A[i][1], B[1][j]));
}

__global__ void vqc_kernel(const float* __restrict__ ms, const float* __restrict__ qw,
                           float* __restrict__ qfeat) {
    int b = blockIdx.x;
    __shared__ c2f psi[1024];
    __shared__ float red[512];
    __shared__ float sang[40];
    int tid = threadIdx.x;
    const float PI_F = 3.14159265358979323846f;
    psi[tid] = { 0.03125f, 0.f };
    psi[tid + 512] = { 0.03125f, 0.f };
    if (tid < 40) sang[tid] = tanhf(ms[b * DM + tid]) * PI_F;
    __syncthreads();

    for (int layer = 0; layer < 4; layer++) {
        for (int q = 0; q < 10; q++) {
            int idx = layer * 10 + q;
            float a = sang[idx];
            float w0 = qw[idx * 3 + 0], w1 = qw[idx * 3 + 1], w2 = qw[idx * 3 + 2];
            float ch, sh; sincosf(0.5f * a, &sh, &ch);
            c2f Rx[2][2] = { { {ch, 0.f}, {0.f, -sh} }, { {0.f, -sh}, {ch, 0.f} } };
            c2f Rya[2][2] = { { {ch, 0.f}, {-sh, 0.f} }, { {sh, 0.f}, {ch, 0.f} } };
            c2f T1[2][2]; matmul2(T1, Rya, Rx);
            float c0, s0; sincosf(0.5f * w0, &s0, &c0);
            c2f Rz0[2][2] = { { {c0, -s0}, {0.f, 0.f} }, { {0.f, 0.f}, {c0, s0} } };
            c2f T2[2][2]; matmul2(T2, Rz0, T1);
            float c1, s1; sincosf(0.5f * w1, &s1, &c1);
            c2f Ry1[2][2] = { { {c1, 0.f}, {-s1, 0.f} }, { {s1, 0.f}, {c1, 0.f} } };
            c2f T3[2][2]; matmul2(T3, Ry1, T2);
            float c2r, s2r; sincosf(0.5f * w2, &s2r, &c2r);
            c2f Rz2[2][2] = { { {c2r, -s2r}, {0.f, 0.f} }, { {0.f, 0.f}, {c2r, s2r} } };
            c2f U[2][2]; matmul2(U, Rz2, T3);

            int bq = 9 - q;
            int low = tid & ((1 << bq) - 1);
            int i0 = ((tid >> bq) << (bq + 1)) | low;
            int i1 = i0 | (1 << bq);
            __syncthreads();
            c2f a0 = psi[i0], a1 = psi[i1];
            psi[i0] = cadd(cmul(U[0][0], a0), cmul(U[0][1], a1));
            psi[i1] = cadd(cmul(U[1][0], a0), cmul(U[1][1], a1));
        }
        for (int qq = 0; qq < 10; qq++) {
            int ctrl = (qq < 9) ? qq : 9;
            int tgt  = (qq < 9) ? qq + 1 : 0;
            int bc = 9 - ctrl, bt = 9 - tgt;
            __syncthreads();
            if (tid < 256) {
                int lo = min(bc, bt), hi = max(bc, bt);
                int i = tid;
                i = ((i >> lo) << (lo + 1)) | (i & ((1 << lo) - 1));
                i = ((i >> hi) << (hi + 1)) | (i & ((1 << hi) - 1));
                i |= (1 << bc);
                int j0 = i;
                int j1 = i | (1 << bt);
                c2f tmp = psi[j0]; psi[j0] = psi[j1]; psi[j1] = tmp;
            }
        }
    }
    __syncthreads();
    c2f p0 = psi[tid], p1 = psi[tid + 512];
    float n0 = p0.x * p0.x + p0.y * p0.y;
    float n1 = p1.x * p1.x + p1.y * p1.y;
    for (int k = 0; k < 10; k++) {
        int bp = 9 - k;
        float s0v = ((tid >> bp) & 1) ? -n0 : n0;
        float s1v = (((tid + 512) >> bp) & 1) ? -n1 : n1;
        red[tid] = s0v + s1v;
        __syncthreads();
        for (int s = 256; s > 0; s >>= 1) { if (tid < s) red[tid] += red[tid + s]; __syncthreads(); }
        if (tid == 0) qfeat[b * 10 + k] = red[0];
        __syncthreads();
    }
}

// ---------------- host launch ----------------
#define GETSYM(p, sym) do { void* _t = nullptr; cudaGetSymbolAddress(&_t, sym); (p) = (float*)_t; } while (0)

extern "C" void kernel_launch(void* const* d_in, const int* in_sizes, int n_in,
                              void* d_out, int out_size) {
    const float* s          = (const float*)d_in[0];
    const float* lstm_s     = (const float*)d_in[1];
    const float* W_ih       = (const float*)d_in[2];
    const float* W_hh       = (const float*)d_in[3];
    const float* b_ih       = (const float*)d_in[4];
    const float* b_hh       = (const float*)d_in[5];
    const float* proj_W     = (const float*)d_in[6];
    const float* proj_b     = (const float*)d_in[7];
    const float* in_proj_W  = (const float*)d_in[8];
    const float* in_proj_b  = (const float*)d_in[9];
    const float* out_proj_W = (const float*)d_in[10];
    const float* out_proj_b = (const float*)d_in[11];
    const float* qweights   = (const float*)d_in[12];
    const float* W1         = (const float*)d_in[13];
    const float* b1         = (const float*)d_in[14];
    const float* W2         = (const float*)d_in[15];
    const float* b2         = (const float*)d_in[16];
    float* out = (float*)d_out;

    float *Wip, *Wp, *bp, *sf, *qv, *qk, *Mkp, *MA1, *Amat;
    float *vconst, *aconst, *hbar, *ao, *msb, *qfeat, *merged, *x1;
    __half *xw, *hbuf, *hs;
    int* bar;
    { void* _t = nullptr; cudaGetSymbolAddress(&_t, d_xw); xw = (__half*)_t; }
    { void* _t = nullptr; cudaGetSymbolAddress(&_t, d_hbuf); hbuf = (__half*)_t; }
    { void* _t = nullptr; cudaGetSymbolAddress(&_t, d_hs); hs = (__half*)_t; }
    GETSYM(Wip, d_Wip); GETSYM(Wp, d_Wp);   GETSYM(bp, d_bp);   GETSYM(sf, d_sf);
    GETSYM(qv, d_q);    GETSYM(qk, d_qk);   GETSYM(Mkp, d_Mkp); GETSYM(MA1, d_MA1);
    GETSYM(Amat, d_Amat); GETSYM(vconst, d_vconst); GETSYM(aconst, d_aconst);
    GETSYM(hbar, d_hbar); GETSYM(ao, d_ao); GETSYM(msb, d_ms);  GETSYM(qfeat, d_qfeat);
    GETSYM(merged, d_merged); GETSYM(x1, d_x1);
    { void* _t = nullptr; cudaGetSymbolAddress(&_t, d_bar); bar = (int*)_t; }

    const float* Wq = in_proj_W;
    const float* Wk = in_proj_W + EDIM * EDIM;
    const float* Wv = in_proj_W + 2 * EDIM * EDIM;
    const float* bq = in_proj_b;
    const float* bv = in_proj_b + 2 * EDIM;

    cudaMemsetAsync(bar, 0, 16 * TSEQ * sizeof(int));

    // weight permutation (gate-interleaved)
    permute_kernel<<<G4, 128>>>(W_ih, W_hh, b_ih, b_hh, Wip, Wp, bp);

    // big input GEMM (fp16 tensor cores): xw[t,b,:] = X @ Wip^T + bp (fp16 out)
    xw_gemm_f16<<<dim3(G4 / 128, (BATCH * TSEQ) / 128), 256>>>(lstm_s, Wip, bp, xw);

    // persistent LSTM recurrence (dual-group interleaved)
    lstm_persist<<<NBLK, 256>>>(xw, Wp, hs, hbuf, bar);

    // state_full = [h_last, s]; q = sf @ Wq^T + bq
    sf_build<<<(BATCH * EDIM + 255) / 256, 256>>>(hs, s, sf);
    gemm_med<false, false><<<dim3(5, 8), 256>>>(sf, Wq, bq, qv, BATCH, EDIM, EDIM, EDIM, EDIM, EDIM);

    // precompose attention matrices
    gemm_med<true, false><<<dim3(4, 5), 256>>>(Wk, proj_W, nullptr, Mkp, EDIM, HID, EDIM, EDIM, HID, HID);
    gemm_med<true, false><<<dim3(4, 8), 256>>>(qv, Mkp, nullptr, qk, BATCH, HID, EDIM, EDIM, HID, HID);
    gemm_med<true, false><<<dim3(4, 5), 256>>>(Wv, proj_W, nullptr, MA1, EDIM, HID, EDIM, EDIM, HID, HID);
    gemm_med<true, false><<<dim3(4, 5), 256>>>(out_proj_W, MA1, nullptr, Amat, EDIM, HID, EDIM, EDIM, HID, HID);
    matvec<<<1, EDIM>>>(Wv, proj_b, bv, vconst, EDIM, EDIM, EDIM);
    matvec<<<1, EDIM>>>(out_proj_W, vconst, out_proj_b, aconst, EDIM, EDIM, EDIM);

    // fused attention over hs
    attn_kernel<<<BATCH, 256>>>(hs, qk, hbar);

    // attn_out = hbar @ Amat^T + aconst; merged_state = [attn_out, s]
    gemm_med<false, false><<<dim3(5, 8), 256>>>(hbar, Amat, aconst, ao, BATCH, EDIM, HID, HID, HID, EDIM);
    ms_build<<<(BATCH * DM + 255) / 256, 256>>>(ao, s, msb);

    // VQC
    vqc_kernel<<<BATCH, 512>>>(msb, qweights, qfeat);

    // MLP
    merged_build<<<(BATCH * NMERG + 255) / 256, 256>>>(msb, qfeat, merged);
    gemm_med<false, true><<<dim3(8, 8), 256>>>(merged, W1, b1, x1, BATCH, NL1, NMERG, NMERG, NMERG, NL1);
    gemm_med<false, false><<<dim3(1, 8), 256>>>(x1, W2, b2, out, BATCH, NACT, NL1, NL1, NL1, NACT);
}

// round 9
// speedup vs baseline: 1.3357x; 1.3357x over previous
#include <cuda_runtime.h>
#include <cuda_fp16.h>
#include <math.h>
#include <stdint.h>

#define BATCH 512
#define TSEQ  256
#define DIN   128
#define HID   256
#define G4    1024
#define FDIM  64
#define EDIM  320
#define DM    384
#define NMERG 394
#define NL1   512
#define NACT  8

#define NBLK   128   // persistent grid: 8 batch-tiles x 16 col-tiles
#define NGRP   16    // blocks per batch-group barrier

// ---------------- scratch (static device memory; no allocations) ----------------
__device__ __half d_xw[134217728];     // [T, B, 4H] fp16 pre-activations (permuted gates)
__device__ __half d_hs[33554432];      // [B, T, H] fp16 hidden states
__device__ __half d_hbuf[2 * BATCH * HID]; // double-buffered compact h (fp16)
__device__ int   d_bar[8 * TSEQ];      // per (batch-group, step) barrier counters
__device__ float d_Wip[G4 * DIN];      // permuted W_ih
__device__ float d_Wp[G4 * HID];       // permuted W_hh
__device__ float d_bp[G4];             // permuted bias
__device__ float d_sf[BATCH * EDIM];   // state_full
__device__ float d_q[BATCH * EDIM];
__device__ float d_qk[BATCH * HID];
__device__ float d_Mkp[EDIM * HID];    // Wk @ proj_W
__device__ float d_MA1[EDIM * HID];    // Wv @ proj_W
__device__ float d_Amat[EDIM * HID];   // Wo @ Wv @ proj_W
__device__ float d_vconst[EDIM];
__device__ float d_aconst[EDIM];
__device__ float d_hbar[BATCH * HID];
__device__ float d_ao[BATCH * EDIM];
__device__ float d_ms[BATCH * DM];
__device__ float d_qfeat[BATCH * 10];
__device__ float d_merged[BATCH * NMERG];
__device__ float d_x1[BATCH * NL1];

// ---------------- fp16 mma helpers ----------------
__device__ __forceinline__ uint32_t pack_h2(float x, float y) {
    __half2 t = __floats2half2_rn(x, y);
    return *reinterpret_cast<uint32_t*>(&t);
}
__device__ __forceinline__ void mma_f16(float* c, uint32_t a0, uint32_t a1,
                                        uint32_t a2, uint32_t a3,
                                        uint32_t b0, uint32_t b1) {
    asm volatile("mma.sync.aligned.m16n8k16.row.col.f32.f16.f16.f32 "
        "{%0,%1,%2,%3}, {%4,%5,%6,%7}, {%8,%9}, {%0,%1,%2,%3};"
        : "+f"(c[0]), "+f"(c[1]), "+f"(c[2]), "+f"(c[3])
        : "r"(a0), "r"(a1), "r"(a2), "r"(a3), "r"(b0), "r"(b1));
}
__device__ __forceinline__ float fsig(float x) {
    return __fdividef(1.f, 1.f + __expf(-x));
}
__device__ __forceinline__ float ftanh(float x) {
    return 2.f * fsig(2.f * x) - 1.f;
}

// ---------------- weight permutation: column 4u+g = gate g of unit u ----------------
__global__ void permute_kernel(const float* __restrict__ W_ih, const float* __restrict__ W_hh,
                               const float* __restrict__ b_ih, const float* __restrict__ b_hh,
                               float* __restrict__ Wip, float* __restrict__ Wp, float* __restrict__ bp) {
    int n = blockIdx.x;            // 0..1023, permuted row
    int u = n >> 2, g = n & 3;
    int o = g * HID + u;           // original row
    for (int k = threadIdx.x; k < DIN; k += blockDim.x) Wip[n * DIN + k] = W_ih[o * DIN + k];
    for (int k = threadIdx.x; k < HID; k += blockDim.x) Wp[n * HID + k] = W_hh[o * HID + k];
    if (threadIdx.x == 0) bp[n] = b_ih[o] + b_hh[o];
}

// ---------------- big input GEMM (fp16 mma): xw[t,b,:] = X[b,t,:] @ Wip^T + bp -------
__global__ __launch_bounds__(256) void xw_gemm_f16(
    const float* __restrict__ X, const float* __restrict__ Wip,
    const float* __restrict__ bp, __half* __restrict__ xw) {
    __shared__ __half sA[128][72];
    __shared__ __half sB[128][72];
    int m0 = blockIdx.y * 128;
    int n0 = blockIdx.x * 128;
    int tid = threadIdx.x;
    int wid = tid >> 5, lane = tid & 31;
    int g = lane >> 2, t4 = lane & 3;
    int warp_m = (wid & 1) * 64;
    int warp_n = (wid >> 1) * 32;

    float c[4][4][4];
    #pragma unroll
    for (int i = 0; i < 4; i++)
        #pragma unroll
        for (int j = 0; j < 4; j++)
            #pragma unroll
            for (int e = 0; e < 4; e++) c[i][j][e] = 0.f;

    for (int k0 = 0; k0 < DIN; k0 += 64) {
        #pragma unroll
        for (int it = 0; it < 8; it++) {
            int gi = it * 256 + tid;
            int row = gi >> 4;
            int c4 = gi & 15;
            {
                float4 v = __ldg((const float4*)(X + (size_t)(m0 + row) * DIN + k0 + c4 * 4));
                uint2 pk = { pack_h2(v.x, v.y), pack_h2(v.z, v.w) };
                *(uint2*)&sA[row][c4 * 4] = pk;
            }
            {
                float4 v = __ldg((const float4*)(Wip + (size_t)(n0 + row) * DIN + k0 + c4 * 4));
                uint2 pk = { pack_h2(v.x, v.y), pack_h2(v.z, v.w) };
                *(uint2*)&sB[row][c4 * 4] = pk;
            }
        }
        __syncthreads();
        #pragma unroll
        for (int kk = 0; kk < 4; kk++) {
            uint32_t br[4][2];
            #pragma unroll
            for (int j = 0; j < 4; j++) {
                const __half* bsrc = &sB[warp_n + 8 * j + g][kk * 16 + 2 * t4];
                br[j][0] = *(const uint32_t*)bsrc;
                br[j][1] = *(const uint32_t*)(bsrc + 8);
            }
            #pragma unroll
            for (int i = 0; i < 4; i++) {
                int r0 = warp_m + 16 * i + g;
                const __half* alo = &sA[r0][kk * 16 + 2 * t4];
                const __half* ahi = &sA[r0 + 8][kk * 16 + 2 * t4];
                uint32_t a0 = *(const uint32_t*)alo;
                uint32_t a2 = *(const uint32_t*)(alo + 8);
                uint32_t a1 = *(const uint32_t*)ahi;
                uint32_t a3 = *(const uint32_t*)(ahi + 8);
                #pragma unroll
                for (int j = 0; j < 4; j++)
                    mma_f16(c[i][j], a0, a1, a2, a3, br[j][0], br[j][1]);
            }
        }
        __syncthreads();
    }

    float2 bb[4];
    #pragma unroll
    for (int j = 0; j < 4; j++) {
        int col = n0 + warp_n + 8 * j + 2 * t4;
        bb[j].x = __ldg(bp + col); bb[j].y = __ldg(bp + col + 1);
    }
    #pragma unroll
    for (int i = 0; i < 4; i++) {
        int rlo = m0 + warp_m + 16 * i + g;
        int rhi = rlo + 8;
        __half* dlo = xw + ((size_t)(rlo & 255) * BATCH + (rlo >> 8)) * G4;
        __half* dhi = xw + ((size_t)(rhi & 255) * BATCH + (rhi >> 8)) * G4;
        #pragma unroll
        for (int j = 0; j < 4; j++) {
            int col = n0 + warp_n + 8 * j + 2 * t4;
            __half2 vlo = __floats2half2_rn(c[i][j][0] + bb[j].x, c[i][j][1] + bb[j].y);
            __half2 vhi = __floats2half2_rn(c[i][j][2] + bb[j].x, c[i][j][3] + bb[j].y);
            *(__half2*)(dlo + col) = vlo;
            *(__half2*)(dhi + col) = vhi;
        }
    }
}

// ---------------- persistent LSTM recurrence: fp16 mma, xw prefetch ------------------
// 128 blocks (by=batch-tile of 64, bx=gatecol-tile of 64), 256 threads = 8 warps.
// Warp tile m32 x n16 via mma.m16n8k16. Wp fragments register-resident; h fp16.
// xw gates for step t+1 prefetched into registers during the step-t barrier spin.
__global__ __launch_bounds__(256, 1) void lstm_persist(
    const __half* __restrict__ xw, const float* __restrict__ Wp,
    __half* __restrict__ hs, __half* __restrict__ hbuf, int* __restrict__ bar)
{
    __shared__ __half sA[64][264];
    int bx = blockIdx.x & 15;       // col tile
    int by = blockIdx.x >> 4;       // batch tile (group id)
    int n0 = bx * 64, m0 = by * 64;
    int tid = threadIdx.x;
    int wid = tid >> 5, lane = tid & 31;
    int g = lane >> 2, t4 = lane & 3;
    int warp_m = (wid & 1) * 32;
    int warp_n = (wid >> 1) * 16;
    int odd = lane & 1;

    // ---- preload B fragments (Wp^T, col-major k16 x n8) into registers, fp16 ----
    uint32_t breg[2][16][2];
    #pragma unroll
    for (int j = 0; j < 2; j++) {
        int col = n0 + warp_n + 8 * j + g;
        const float* wrow = Wp + (size_t)col * HID;
        #pragma unroll
        for (int kk = 0; kk < 16; kk++) {
            breg[j][kk][0] = pack_h2(__ldg(wrow + kk * 16 + 2 * t4),
                                     __ldg(wrow + kk * 16 + 2 * t4 + 1));
            breg[j][kk][1] = pack_h2(__ldg(wrow + kk * 16 + 2 * t4 + 8),
                                     __ldg(wrow + kk * 16 + 2 * t4 + 9));
        }
    }
    float creg[4] = {0.f, 0.f, 0.f, 0.f};
    volatile int* vbar = bar;

    // epilogue row/unit coords
    int erow[2], eu;
    erow[0] = m0 + warp_m + g + (odd ? 8 : 0);
    erow[1] = erow[0] + 16;
    eu = ((n0 + warp_n) >> 2) + ((lane >> 1) & 1);

    // prefetch xw gates for t=0
    uint2 xg[2][2];
    #pragma unroll
    for (int i = 0; i < 2; i++)
        #pragma unroll
        for (int j = 0; j < 2; j++)
            xg[i][j] = __ldg((const uint2*)(xw + (size_t)erow[i] * G4 + 4 * (eu + 2 * j)));

    for (int t = 0; t < TSEQ; t++) {
        float c[2][2][4];
        #pragma unroll
        for (int i = 0; i < 2; i++)
            #pragma unroll
            for (int j = 0; j < 2; j++)
                #pragma unroll
                for (int e = 0; e < 4; e++) c[i][j][e] = 0.f;

        if (t > 0) {
            const __half* hp = hbuf + (size_t)(t & 1) * (BATCH * HID);
            // fill: 64 rows x 256 halves = 32 KB; one uint4 per thread x 8 iters
            #pragma unroll
            for (int itr = 0; itr < 8; itr++) {
                int gi = itr * 256 + tid;
                int row = gi >> 5;
                int s2 = gi & 31;
                uint4 v = __ldcg((const uint4*)(hp + (size_t)(m0 + row) * HID + s2 * 8));
                *(uint4*)&sA[row][s2 * 8] = v;
            }
            __syncthreads();
            #pragma unroll
            for (int kk = 0; kk < 16; kk++) {
                #pragma unroll
                for (int i = 0; i < 2; i++) {
                    int r0 = warp_m + 16 * i + g;
                    const __half* alo = &sA[r0][kk * 16 + 2 * t4];
                    const __half* ahi = &sA[r0 + 8][kk * 16 + 2 * t4];
                    uint32_t a0 = *(const uint32_t*)alo;
                    uint32_t a2 = *(const uint32_t*)(alo + 8);
                    uint32_t a1 = *(const uint32_t*)ahi;
                    uint32_t a3 = *(const uint32_t*)(ahi + 8);
                    mma_f16(c[i][0], a0, a1, a2, a3, breg[0][kk][0], breg[0][kk][1]);
                    mma_f16(c[i][1], a0, a1, a2, a3, breg[1][kk][0], breg[1][kk][1]);
                }
            }
        }

        // ---- epilogue: gate exchange via shfl, cell update (prefetched xw) ----
        __half* hn = hbuf + (size_t)((t + 1) & 1) * (BATCH * HID);
        float hvreg[2][2];
        #pragma unroll
        for (int i = 0; i < 2; i++) {
            #pragma unroll
            for (int j = 0; j < 2; j++) {
                float u0 = odd ? c[i][j][0] : c[i][j][2];
                float u1 = odd ? c[i][j][1] : c[i][j][3];
                float rx0 = __shfl_xor_sync(0xffffffffu, u0, 1);
                float rx1 = __shfl_xor_sync(0xffffffffu, u1, 1);
                float gi, gf, gg, go;
                if (!odd) { gi = c[i][j][0]; gf = c[i][j][1]; gg = rx0; go = rx1; }
                else      { gi = rx0; gf = rx1; gg = c[i][j][2]; go = c[i][j][3]; }
                int brow = erow[i];
                int u = eu + 2 * j;
                float2 f01 = __half22float2(*reinterpret_cast<__half2*>(&xg[i][j].x));
                float2 f23 = __half22float2(*reinterpret_cast<__half2*>(&xg[i][j].y));
                gi += f01.x; gf += f01.y; gg += f23.x; go += f23.y;
                float i_ = fsig(gi);
                float f_ = fsig(gf);
                float g_ = ftanh(gg);
                float o_ = fsig(go);
                int ci = i * 2 + j;
                float cn = f_ * creg[ci] + i_ * g_;
                creg[ci] = cn;
                float hv = o_ * ftanh(cn);
                hvreg[i][j] = hv;
                hn[(size_t)brow * HID + u] = __float2half_rn(hv);
            }
        }

        // arrive ASAP; prefetch next xw + archive hs while peers arrive; then wait
        int bi = by * TSEQ + t;
        if (t < TSEQ - 1) {
            __threadfence();
            __syncthreads();
            if (tid == 0) atomicAdd(&bar[bi], 1);
            // prefetch next step's xw gates (DRAM latency hides behind spin)
            const __half* xwn = xw + (size_t)(t + 1) * BATCH * G4;
            #pragma unroll
            for (int i = 0; i < 2; i++)
                #pragma unroll
                for (int j = 0; j < 2; j++)
                    xg[i][j] = __ldg((const uint2*)(xwn + (size_t)erow[i] * G4 + 4 * (eu + 2 * j)));
        }
        #pragma unroll
        for (int i = 0; i < 2; i++)
            #pragma unroll
            for (int j = 0; j < 2; j++)
                hs[((size_t)erow[i] * TSEQ + t) * HID + eu + 2 * j] = __float2half_rn(hvreg[i][j]);
        if (t < TSEQ - 1) {
            if (tid == 0) { while (vbar[bi] < NGRP) {} }
            __syncthreads();
        }
    }
}

// ---------------- medium GEMM: C = A @ op(W) + bias, opt relu ------------------------
template <bool TRANS, bool RELU>
__global__ __launch_bounds__(256) void gemm_med(
    const float* __restrict__ A, const float* __restrict__ W,
    const float* __restrict__ bias, float* __restrict__ C,
    int M, int N, int K, int lda, int ldw, int ldc) {
    __shared__ float sA[16][68];
    __shared__ float sW[16][68];
    int m0 = blockIdx.y * 64, n0 = blockIdx.x * 64;
    int tid = threadIdx.x;
    int tx = tid & 15, ty = tid >> 4;
    float acc[4][4] = {};
    for (int k0 = 0; k0 < K; k0 += 16) {
        #pragma unroll
        for (int i = 0; i < 4; i++) {
            int idx = tid + i * 256;
            int r = idx >> 4, k = idx & 15;
            int mm = m0 + r, kk = k0 + k;
            sA[k][r] = (mm < M && kk < K) ? A[(size_t)mm * lda + kk] : 0.f;
            int nn = n0 + r;
            float v = 0.f;
            if (TRANS) { if (kk < K && nn < N) v = W[(size_t)kk * ldw + nn]; }
            else       { if (nn < N && kk < K) v = W[(size_t)nn * ldw + kk]; }
            sW[k][r] = v;
        }
        __syncthreads();
        #pragma unroll
        for (int k = 0; k < 16; k++) {
            float4 a = *(const float4*)&sA[k][ty * 4];
            float4 b = *(const float4*)&sW[k][tx * 4];
            acc[0][0] += a.x * b.x; acc[0][1] += a.x * b.y; acc[0][2] += a.x * b.z; acc[0][3] += a.x * b.w;
            acc[1][0] += a.y * b.x; acc[1][1] += a.y * b.y; acc[1][2] += a.y * b.z; acc[1][3] += a.y * b.w;
            acc[2][0] += a.z * b.x; acc[2][1] += a.z * b.y; acc[2][2] += a.z * b.z; acc[2][3] += a.z * b.w;
            acc[3][0] += a.w * b.x; acc[3][1] += a.w * b.y; acc[3][2] += a.w * b.z; acc[3][3] += a.w * b.w;
        }
        __syncthreads();
    }
    #pragma unroll
    for (int r = 0; r < 4; r++) {
        int m = m0 + ty * 4 + r;
        if (m >= M) continue;
        #pragma unroll
        for (int cc = 0; cc < 4; cc++) {
            int n = n0 + tx * 4 + cc;
            if (n >= N) continue;
            float v = acc[r][cc];
            if (bias) v += bias[n];
            if (RELU) v = fmaxf(v, 0.f);
            C[(size_t)m * ldc + n] = v;
        }
    }
}

// ---------------- tiny matvec ----------------
__global__ void matvec(const float* __restrict__ W, const float* __restrict__ x,
                       const float* __restrict__ bias, float* __restrict__ y,
                       int N, int K, int ldw) {
    int i = blockIdx.x * blockDim.x + threadIdx.x;
    if (i >= N) return;
    float a = bias ? bias[i] : 0.f;
    for (int k = 0; k < K; k++) a += W[(size_t)i * ldw + k] * x[k];
    y[i] = a;
}

// ---------------- fused attention over fp16 hs ---------------------------------------
__global__ void attn_kernel(const __half* __restrict__ hs, const float* __restrict__ qk,
                            float* __restrict__ hbar) {
    int b = blockIdx.x;
    __shared__ float sc[TSEQ];
    __shared__ float red[256];
    __shared__ float sqk[HID];
    int tid = threadIdx.x;
    int lane = tid & 31, w = tid >> 5;
    sqk[tid] = qk[b * HID + tid];
    __syncthreads();
    for (int t = w; t < TSEQ; t += 8) {
        const __half2* hrow = (const __half2*)(hs + ((size_t)b * TSEQ + t) * HID);
        float p = 0.f;
        #pragma unroll
        for (int j = 0; j < 4; j++) {
            int h2i = lane + 32 * j;
            float2 hv = __half22float2(hrow[h2i]);
            p += hv.x * sqk[2 * h2i] + hv.y * sqk[2 * h2i + 1];
        }
        #pragma unroll
        for (int o = 16; o > 0; o >>= 1) p += __shfl_down_sync(0xffffffffu, p, o);
        if (lane == 0) sc[t] = p;
    }
    __syncthreads();
    float scale = 1.0f / sqrtf((float)EDIM);
    float v = sc[tid] * scale;
    red[tid] = v; __syncthreads();
    for (int s = 128; s > 0; s >>= 1) { if (tid < s) red[tid] = fmaxf(red[tid], red[tid + s]); __syncthreads(); }
    float mx = red[0]; __syncthreads();
    float ev = expf(v - mx);
    red[tid] = ev; __syncthreads();
    for (int s = 128; s > 0; s >>= 1) { if (tid < s) red[tid] += red[tid + s]; __syncthreads(); }
    float sum = red[0]; __syncthreads();
    sc[tid] = ev / sum;
    __syncthreads();
    const __half* hb = hs + (size_t)b * TSEQ * HID;
    float acc = 0.f;
    for (int t = 0; t < TSEQ; t++) acc += sc[t] * __half2float(hb[(size_t)t * HID + tid]);
    hbar[b * HID + tid] = acc;
}

// ---------------- concat helpers ----------------
__global__ void sf_build(const __half* __restrict__ hs, const float* __restrict__ s,
                         float* __restrict__ sf) {
    int idx = blockIdx.x * blockDim.x + threadIdx.x;
    if (idx >= BATCH * EDIM) return;
    int b = idx / EDIM, j = idx % EDIM;
    sf[idx] = (j < HID) ? __half2float(hs[((size_t)b * TSEQ + (TSEQ - 1)) * HID + j])
                        : s[b * FDIM + (j - HID)];
}
__global__ void ms_build(const float* __restrict__ ao, const float* __restrict__ s,
                         float* __restrict__ ms) {
    int idx = blockIdx.x * blockDim.x + threadIdx.x;
    if (idx >= BATCH * DM) return;
    int b = idx / DM, j = idx % DM;
    ms[idx] = (j < EDIM) ? ao[b * EDIM + j] : s[b * FDIM + (j - EDIM)];
}
__global__ void merged_build(const float* __restrict__ ms, const float* __restrict__ qf,
                             float* __restrict__ mg) {
    int idx = blockIdx.x * blockDim.x + threadIdx.x;
    if (idx >= BATCH * NMERG) return;
    int b = idx / NMERG, j = idx % NMERG;
    mg[idx] = (j < DM) ? ms[b * DM + j] : qf[b * 10 + (j - DM)];
}

// ---------------- 10-qubit VQC, one block per batch element --------------------------
struct c2f { float x, y; };
__device__ __forceinline__ c2f cmul(c2f a, c2f b) { return { a.x * b.x - a.y * b.y, a.x * b.y + a.y * b.x }; }
__device__ __forceinline__ c2f cadd(c2f a, c2f b) { return { a.x + b.x, a.y + b.y }; }
__device__ __forceinline__ void matmul2(c2f C[2][2], const c2f A[2][2], const c2f B[2][2]) {
    #pragma unroll
    for (int i = 0; i < 2; i++)
        #pragma unroll
        for (int j = 0; j < 2; j++)
            C[i][j] = cadd(cmul(A[i][0], B[0][j]), cmul(A[i][1], B[1][j]));
}

__global__ void vqc_kernel(const float* __restrict__ ms, const float* __restrict__ qw,
                           float* __restrict__ qfeat) {
    int b = blockIdx.x;
    __shared__ c2f psi[1024];
    __shared__ float red[512];
    __shared__ float sang[40];
    int tid = threadIdx.x;
    const float PI_F = 3.14159265358979323846f;
    psi[tid] = { 0.03125f, 0.f };
    psi[tid + 512] = { 0.03125f, 0.f };
    if (tid < 40) sang[tid] = tanhf(ms[b * DM + tid]) * PI_F;
    __syncthreads();

    for (int layer = 0; layer < 4; layer++) {
        for (int q = 0; q < 10; q++) {
            int idx = layer * 10 + q;
            float a = sang[idx];
            float w0 = qw[idx * 3 + 0], w1 = qw[idx * 3 + 1], w2 = qw[idx * 3 + 2];
            float ch, sh; sincosf(0.5f * a, &sh, &ch);
            c2f Rx[2][2] = { { {ch, 0.f}, {0.f, -sh} }, { {0.f, -sh}, {ch, 0.f} } };
            c2f Rya[2][2] = { { {ch, 0.f}, {-sh, 0.f} }, { {sh, 0.f}, {ch, 0.f} } };
            c2f T1[2][2]; matmul2(T1, Rya, Rx);
            float c0, s0; sincosf(0.5f * w0, &s0, &c0);
            c2f Rz0[2][2] = { { {c0, -s0}, {0.f, 0.f} }, { {0.f, 0.f}, {c0, s0} } };
            c2f T2[2][2]; matmul2(T2, Rz0, T1);
            float c1, s1; sincosf(0.5f * w1, &s1, &c1);
            c2f Ry1[2][2] = { { {c1, 0.f}, {-s1, 0.f} }, { {s1, 0.f}, {c1, 0.f} } };
            c2f T3[2][2]; matmul2(T3, Ry1, T2);
            float c2r, s2r; sincosf(0.5f * w2, &s2r, &c2r);
            c2f Rz2[2][2] = { { {c2r, -s2r}, {0.f, 0.f} }, { {0.f, 0.f}, {c2r, s2r} } };
            c2f U[2][2]; matmul2(U, Rz2, T3);

            int bq = 9 - q;
            int low = tid & ((1 << bq) - 1);
            int i0 = ((tid >> bq) << (bq + 1)) | low;
            int i1 = i0 | (1 << bq);
            __syncthreads();
            c2f a0 = psi[i0], a1 = psi[i1];
            psi[i0] = cadd(cmul(U[0][0], a0), cmul(U[0][1], a1));
            psi[i1] = cadd(cmul(U[1][0], a0), cmul(U[1][1], a1));
        }
        for (int qq = 0; qq < 10; qq++) {
            int ctrl = (qq < 9) ? qq : 9;
            int tgt  = (qq < 9) ? qq + 1 : 0;
            int bc = 9 - ctrl, bt = 9 - tgt;
            __syncthreads();
            if (tid < 256) {
                int lo = min(bc, bt), hi = max(bc, bt);
                int i = tid;
                i = ((i >> lo) << (lo + 1)) | (i & ((1 << lo) - 1));
                i = ((i >> hi) << (hi + 1)) | (i & ((1 << hi) - 1));
                i |= (1 << bc);
                int j0 = i;
                int j1 = i | (1 << bt);
                c2f tmp = psi[j0]; psi[j0] = psi[j1]; psi[j1] = tmp;
            }
        }
    }
    __syncthreads();
    c2f p0 = psi[tid], p1 = psi[tid + 512];
    float n0 = p0.x * p0.x + p0.y * p0.y;
    float n1 = p1.x * p1.x + p1.y * p1.y;
    for (int k = 0; k < 10; k++) {
        int bp = 9 - k;
        float s0v = ((tid >> bp) & 1) ? -n0 : n0;
        float s1v = (((tid + 512) >> bp) & 1) ? -n1 : n1;
        red[tid] = s0v + s1v;
        __syncthreads();
        for (int s = 256; s > 0; s >>= 1) { if (tid < s) red[tid] += red[tid + s]; __syncthreads(); }
        if (tid == 0) qfeat[b * 10 + k] = red[0];
        __syncthreads();
    }
}

// ---------------- host launch ----------------
#define GETSYM(p, sym) do { void* _t = nullptr; cudaGetSymbolAddress(&_t, sym); (p) = (float*)_t; } while (0)

extern "C" void kernel_launch(void* const* d_in, const int* in_sizes, int n_in,
                              void* d_out, int out_size) {
    const float* s          = (const float*)d_in[0];
    const float* lstm_s     = (const float*)d_in[1];
    const float* W_ih       = (const float*)d_in[2];
    const float* W_hh       = (const float*)d_in[3];
    const float* b_ih       = (const float*)d_in[4];
    const float* b_hh       = (const float*)d_in[5];
    const float* proj_W     = (const float*)d_in[6];
    const float* proj_b     = (const float*)d_in[7];
    const float* in_proj_W  = (const float*)d_in[8];
    const float* in_proj_b  = (const float*)d_in[9];
    const float* out_proj_W = (const float*)d_in[10];
    const float* out_proj_b = (const float*)d_in[11];
    const float* qweights   = (const float*)d_in[12];
    const float* W1         = (const float*)d_in[13];
    const float* b1         = (const float*)d_in[14];
    const float* W2         = (const float*)d_in[15];
    const float* b2         = (const float*)d_in[16];
    float* out = (float*)d_out;

    float *Wip, *Wp, *bp, *sf, *qv, *qk, *Mkp, *MA1, *Amat;
    float *vconst, *aconst, *hbar, *ao, *msb, *qfeat, *merged, *x1;
    __half *xw, *hbuf, *hs;
    int* bar;
    { void* _t = nullptr; cudaGetSymbolAddress(&_t, d_xw); xw = (__half*)_t; }
    { void* _t = nullptr; cudaGetSymbolAddress(&_t, d_hbuf); hbuf = (__half*)_t; }
    { void* _t = nullptr; cudaGetSymbolAddress(&_t, d_hs); hs = (__half*)_t; }
    GETSYM(Wip, d_Wip); GETSYM(Wp, d_Wp);   GETSYM(bp, d_bp);   GETSYM(sf, d_sf);
    GETSYM(qv, d_q);    GETSYM(qk, d_qk);   GETSYM(Mkp, d_Mkp); GETSYM(MA1, d_MA1);
    GETSYM(Amat, d_Amat); GETSYM(vconst, d_vconst); GETSYM(aconst, d_aconst);
    GETSYM(hbar, d_hbar); GETSYM(ao, d_ao); GETSYM(msb, d_ms);  GETSYM(qfeat, d_qfeat);
    GETSYM(merged, d_merged); GETSYM(x1, d_x1);
    { void* _t = nullptr; cudaGetSymbolAddress(&_t, d_bar); bar = (int*)_t; }

    const float* Wq = in_proj_W;
    const float* Wk = in_proj_W + EDIM * EDIM;
    const float* Wv = in_proj_W + 2 * EDIM * EDIM;
    const float* bq = in_proj_b;
    const float* bv = in_proj_b + 2 * EDIM;

    cudaMemsetAsync(bar, 0, 8 * TSEQ * sizeof(int));

    // weight permutation (gate-interleaved)
    permute_kernel<<<G4, 128>>>(W_ih, W_hh, b_ih, b_hh, Wip, Wp, bp);

    // big input GEMM (fp16 tensor cores): xw[t,b,:] = X @ Wip^T + bp (fp16 out)
    xw_gemm_f16<<<dim3(G4 / 128, (BATCH * TSEQ) / 128), 256>>>(lstm_s, Wip, bp, xw);

    // persistent LSTM recurrence (single-group, xw prefetch)
    lstm_persist<<<NBLK, 256>>>(xw, Wp, hs, hbuf, bar);

    // state_full = [h_last, s]; q = sf @ Wq^T + bq
    sf_build<<<(BATCH * EDIM + 255) / 256, 256>>>(hs, s, sf);
    gemm_med<false, false><<<dim3(5, 8), 256>>>(sf, Wq, bq, qv, BATCH, EDIM, EDIM, EDIM, EDIM, EDIM);

    // precompose attention matrices
    gemm_med<true, false><<<dim3(4, 5), 256>>>(Wk, proj_W, nullptr, Mkp, EDIM, HID, EDIM, EDIM, HID, HID);
    gemm_med<true, false><<<dim3(4, 8), 256>>>(qv, Mkp, nullptr, qk, BATCH, HID, EDIM, EDIM, HID, HID);
    gemm_med<true, false><<<dim3(4, 5), 256>>>(Wv, proj_W, nullptr, MA1, EDIM, HID, EDIM, EDIM, HID, HID);
    gemm_med<true, false><<<dim3(4, 5), 256>>>(out_proj_W, MA1, nullptr, Amat, EDIM, HID, EDIM, EDIM, HID, HID);
    matvec<<<1, EDIM>>>(Wv, proj_b, bv, vconst, EDIM, EDIM, EDIM);
    matvec<<<1, EDIM>>>(out_proj_W, vconst, out_proj_b, aconst, EDIM, EDIM, EDIM);

    // fused attention over hs
    attn_kernel<<<BATCH, 256>>>(hs, qk, hbar);

    // attn_out = hbar @ Amat^T + aconst; merged_state = [attn_out, s]
    gemm_med<false, false><<<dim3(5, 8), 256>>>(hbar, Amat, aconst, ao, BATCH, EDIM, HID, HID, HID, EDIM);
    ms_build<<<(BATCH * DM + 255) / 256, 256>>>(ao, s, msb);

    // VQC
    vqc_kernel<<<BATCH, 512>>>(msb, qweights, qfeat);

    // MLP
    merged_build<<<(BATCH * NMERG + 255) / 256, 256>>>(msb, qfeat, merged);
    gemm_med<false, true><<<dim3(8, 8), 256>>>(merged, W1, b1, x1, BATCH, NL1, NMERG, NMERG, NMERG, NL1);
    gemm_med<false, false><<<dim3(1, 8), 256>>>(x1, W2, b2, out, BATCH, NACT, NL1, NL1, NL1, NACT);
}

// round 10
// speedup vs baseline: 1.3747x; 1.0291x over previous
#include <cuda_runtime.h>
#include <cuda_fp16.h>
#include <math.h>
#include <stdint.h>

#define BATCH 512
#define TSEQ  256
#define DIN   128
#define HID   256
#define G4    1024
#define FDIM  64
#define EDIM  320
#define DM    384
#define NMERG 394
#define NL1   512
#define NACT  8

#define NBLK   128   // persistent grid: 16 batch-groups x 8 col-tiles
#define NGRP   8     // blocks per batch-group barrier

// ---------------- scratch (static device memory; no allocations) ----------------
__device__ __half d_xw[134217728];     // [T, B, 4H] fp16 pre-activations (permuted gates)
__device__ __half d_hs[33554432];      // [B, T, H] fp16 hidden states
__device__ __half d_hbuf[2 * BATCH * HID]; // double-buffered compact h (fp16)
__device__ int   d_bar[16 * TSEQ];     // per (batch-group, step) barrier counters
__device__ float d_Wip[G4 * DIN];      // permuted W_ih
__device__ float d_Wp[G4 * HID];       // permuted W_hh
__device__ float d_bp[G4];             // permuted bias
__device__ float d_sf[BATCH * EDIM];   // state_full
__device__ float d_q[BATCH * EDIM];
__device__ float d_qk[BATCH * HID];
__device__ float d_Mkp[EDIM * HID];    // Wk @ proj_W
__device__ float d_MA1[EDIM * HID];    // Wv @ proj_W
__device__ float d_Amat[EDIM * HID];   // Wo @ Wv @ proj_W
__device__ float d_vconst[EDIM];
__device__ float d_aconst[EDIM];
__device__ float d_hbar[BATCH * HID];
__device__ float d_ao[BATCH * EDIM];
__device__ float d_merged[BATCH * NMERG];  // [merged_state | qfeat]
__device__ float d_x1[BATCH * NL1];

// ---------------- fp16 mma helpers ----------------
__device__ __forceinline__ uint32_t pack_h2(float x, float y) {
    __half2 t = __floats2half2_rn(x, y);
    return *reinterpret_cast<uint32_t*>(&t);
}
__device__ __forceinline__ void mma_f16(float* c, uint32_t a0, uint32_t a1,
                                        uint32_t a2, uint32_t a3,
                                        uint32_t b0, uint32_t b1) {
    asm volatile("mma.sync.aligned.m16n8k16.row.col.f32.f16.f16.f32 "
        "{%0,%1,%2,%3}, {%4,%5,%6,%7}, {%8,%9}, {%0,%1,%2,%3};"
        : "+f"(c[0]), "+f"(c[1]), "+f"(c[2]), "+f"(c[3])
        : "r"(a0), "r"(a1), "r"(a2), "r"(a3), "r"(b0), "r"(b1));
}
__device__ __forceinline__ float fsig(float x) {
    return __fdividef(1.f, 1.f + __expf(-x));
}
__device__ __forceinline__ float ftanh(float x) {
    return 2.f * fsig(2.f * x) - 1.f;
}

// ---------------- weight permutation: column 4u+g = gate g of unit u ----------------
__global__ void permute_kernel(const float* __restrict__ W_ih, const float* __restrict__ W_hh,
                               const float* __restrict__ b_ih, const float* __restrict__ b_hh,
                               float* __restrict__ Wip, float* __restrict__ Wp, float* __restrict__ bp) {
    int n = blockIdx.x;            // 0..1023, permuted row
    int u = n >> 2, g = n & 3;
    int o = g * HID + u;           // original row
    for (int k = threadIdx.x; k < DIN; k += blockDim.x) Wip[n * DIN + k] = W_ih[o * DIN + k];
    for (int k = threadIdx.x; k < HID; k += blockDim.x) Wp[n * HID + k] = W_hh[o * HID + k];
    if (threadIdx.x == 0) bp[n] = b_ih[o] + b_hh[o];
}

// ---------------- big input GEMM (fp16 mma): xw[t,b,:] = X[b,t,:] @ Wip^T + bp -------
__global__ __launch_bounds__(256) void xw_gemm_f16(
    const float* __restrict__ X, const float* __restrict__ Wip,
    const float* __restrict__ bp, __half* __restrict__ xw) {
    __shared__ __half sA[128][72];
    __shared__ __half sB[128][72];
    int m0 = blockIdx.y * 128;
    int n0 = blockIdx.x * 128;
    int tid = threadIdx.x;
    int wid = tid >> 5, lane = tid & 31;
    int g = lane >> 2, t4 = lane & 3;
    int warp_m = (wid & 1) * 64;
    int warp_n = (wid >> 1) * 32;

    float c[4][4][4];
    #pragma unroll
    for (int i = 0; i < 4; i++)
        #pragma unroll
        for (int j = 0; j < 4; j++)
            #pragma unroll
            for (int e = 0; e < 4; e++) c[i][j][e] = 0.f;

    for (int k0 = 0; k0 < DIN; k0 += 64) {
        #pragma unroll
        for (int it = 0; it < 8; it++) {
            int gi = it * 256 + tid;
            int row = gi >> 4;
            int c4 = gi & 15;
            {
                float4 v = __ldg((const float4*)(X + (size_t)(m0 + row) * DIN + k0 + c4 * 4));
                uint2 pk = { pack_h2(v.x, v.y), pack_h2(v.z, v.w) };
                *(uint2*)&sA[row][c4 * 4] = pk;
            }
            {
                float4 v = __ldg((const float4*)(Wip + (size_t)(n0 + row) * DIN + k0 + c4 * 4));
                uint2 pk = { pack_h2(v.x, v.y), pack_h2(v.z, v.w) };
                *(uint2*)&sB[row][c4 * 4] = pk;
            }
        }
        __syncthreads();
        #pragma unroll
        for (int kk = 0; kk < 4; kk++) {
            uint32_t br[4][2];
            #pragma unroll
            for (int j = 0; j < 4; j++) {
                const __half* bsrc = &sB[warp_n + 8 * j + g][kk * 16 + 2 * t4];
                br[j][0] = *(const uint32_t*)bsrc;
                br[j][1] = *(const uint32_t*)(bsrc + 8);
            }
            #pragma unroll
            for (int i = 0; i < 4; i++) {
                int r0 = warp_m + 16 * i + g;
                const __half* alo = &sA[r0][kk * 16 + 2 * t4];
                const __half* ahi = &sA[r0 + 8][kk * 16 + 2 * t4];
                uint32_t a0 = *(const uint32_t*)alo;
                uint32_t a2 = *(const uint32_t*)(alo + 8);
                uint32_t a1 = *(const uint32_t*)ahi;
                uint32_t a3 = *(const uint32_t*)(ahi + 8);
                #pragma unroll
                for (int j = 0; j < 4; j++)
                    mma_f16(c[i][j], a0, a1, a2, a3, br[j][0], br[j][1]);
            }
        }
        __syncthreads();
    }

    float2 bb[4];
    #pragma unroll
    for (int j = 0; j < 4; j++) {
        int col = n0 + warp_n + 8 * j + 2 * t4;
        bb[j].x = __ldg(bp + col); bb[j].y = __ldg(bp + col + 1);
    }
    #pragma unroll
    for (int i = 0; i < 4; i++) {
        int rlo = m0 + warp_m + 16 * i + g;
        int rhi = rlo + 8;
        __half* dlo = xw + ((size_t)(rlo & 255) * BATCH + (rlo >> 8)) * G4;
        __half* dhi = xw + ((size_t)(rhi & 255) * BATCH + (rhi >> 8)) * G4;
        #pragma unroll
        for (int j = 0; j < 4; j++) {
            int col = n0 + warp_n + 8 * j + 2 * t4;
            __half2 vlo = __floats2half2_rn(c[i][j][0] + bb[j].x, c[i][j][1] + bb[j].y);
            __half2 vhi = __floats2half2_rn(c[i][j][2] + bb[j].x, c[i][j][3] + bb[j].y);
            *(__half2*)(dlo + col) = vlo;
            *(__half2*)(dhi + col) = vhi;
        }
    }
}

// ---------------- persistent LSTM recurrence: fp16 mma, 16 groups x 8 blocks ---------
// Block = 32 batch rows x 128 gate cols. 8 warps, warp tile m32 x n16 (m16n8k16).
// Wp fragments register-resident; h fp16; xw prefetched during barrier spin.
__global__ __launch_bounds__(256, 1) void lstm_persist(
    const __half* __restrict__ xw, const float* __restrict__ Wp,
    __half* __restrict__ hs, __half* __restrict__ hbuf, int* __restrict__ bar)
{
    __shared__ __half sA[32][264];
    int bx = blockIdx.x & 7;        // col tile (128 cols)
    int gid = blockIdx.x >> 3;      // batch group (0..15, 32 rows)
    int n0 = bx * 128, m0 = gid * 32;
    int tid = threadIdx.x;
    int wid = tid >> 5, lane = tid & 31;
    int g = lane >> 2, t4 = lane & 3;
    int warp_n = wid * 16;
    int odd = lane & 1;

    // ---- preload B fragments (Wp^T, col-major k16 x n8) into registers, fp16 ----
    uint32_t breg[2][16][2];
    #pragma unroll
    for (int j = 0; j < 2; j++) {
        int col = n0 + warp_n + 8 * j + g;
        const float* wrow = Wp + (size_t)col * HID;
        #pragma unroll
        for (int kk = 0; kk < 16; kk++) {
            breg[j][kk][0] = pack_h2(__ldg(wrow + kk * 16 + 2 * t4),
                                     __ldg(wrow + kk * 16 + 2 * t4 + 1));
            breg[j][kk][1] = pack_h2(__ldg(wrow + kk * 16 + 2 * t4 + 8),
                                     __ldg(wrow + kk * 16 + 2 * t4 + 9));
        }
    }
    float creg[4] = {0.f, 0.f, 0.f, 0.f};
    volatile int* vbar = bar;

    // epilogue row/unit coords
    int erow[2], eu;
    erow[0] = m0 + g + (odd ? 8 : 0);
    erow[1] = erow[0] + 16;
    eu = ((n0 + warp_n) >> 2) + ((lane >> 1) & 1);

    // prefetch xw gates for t=0
    uint2 xg[2][2];
    #pragma unroll
    for (int i = 0; i < 2; i++)
        #pragma unroll
        for (int j = 0; j < 2; j++)
            xg[i][j] = __ldg((const uint2*)(xw + (size_t)erow[i] * G4 + 4 * (eu + 2 * j)));

    for (int t = 0; t < TSEQ; t++) {
        float c[2][2][4];
        #pragma unroll
        for (int i = 0; i < 2; i++)
            #pragma unroll
            for (int j = 0; j < 2; j++)
                #pragma unroll
                for (int e = 0; e < 4; e++) c[i][j][e] = 0.f;

        if (t > 0) {
            const __half* hp = hbuf + (size_t)(t & 1) * (BATCH * HID);
            // fill: 32 rows x 256 halves = 16 KB; one uint4 per thread x 4 iters
            #pragma unroll
            for (int itr = 0; itr < 4; itr++) {
                int gi = itr * 256 + tid;
                int row = gi >> 5;
                int s2 = gi & 31;
                uint4 v = __ldcg((const uint4*)(hp + (size_t)(m0 + row) * HID + s2 * 8));
                *(uint4*)&sA[row][s2 * 8] = v;
            }
            __syncthreads();
            #pragma unroll
            for (int kk = 0; kk < 16; kk++) {
                #pragma unroll
                for (int i = 0; i < 2; i++) {
                    int r0 = 16 * i + g;
                    const __half* alo = &sA[r0][kk * 16 + 2 * t4];
                    const __half* ahi = &sA[r0 + 8][kk * 16 + 2 * t4];
                    uint32_t a0 = *(const uint32_t*)alo;
                    uint32_t a2 = *(const uint32_t*)(alo + 8);
                    uint32_t a1 = *(const uint32_t*)ahi;
                    uint32_t a3 = *(const uint32_t*)(ahi + 8);
                    mma_f16(c[i][0], a0, a1, a2, a3, breg[0][kk][0], breg[0][kk][1]);
                    mma_f16(c[i][1], a0, a1, a2, a3, breg[1][kk][0], breg[1][kk][1]);
                }
            }
        }

        // ---- epilogue: gate exchange via shfl, cell update (prefetched xw) ----
        __half* hn = hbuf + (size_t)((t + 1) & 1) * (BATCH * HID);
        float hvreg[2][2];
        #pragma unroll
        for (int i = 0; i < 2; i++) {
            #pragma unroll
            for (int j = 0; j < 2; j++) {
                float u0 = odd ? c[i][j][0] : c[i][j][2];
                float u1 = odd ? c[i][j][1] : c[i][j][3];
                float rx0 = __shfl_xor_sync(0xffffffffu, u0, 1);
                float rx1 = __shfl_xor_sync(0xffffffffu, u1, 1);
                float gi, gf, gg, go;
                if (!odd) { gi = c[i][j][0]; gf = c[i][j][1]; gg = rx0; go = rx1; }
                else      { gi = rx0; gf = rx1; gg = c[i][j][2]; go = c[i][j][3]; }
                int brow = erow[i];
                int u = eu + 2 * j;
                float2 f01 = __half22float2(*reinterpret_cast<__half2*>(&xg[i][j].x));
                float2 f23 = __half22float2(*reinterpret_cast<__half2*>(&xg[i][j].y));
                gi += f01.x; gf += f01.y; gg += f23.x; go += f23.y;
                float i_ = fsig(gi);
                float f_ = fsig(gf);
                float g_ = ftanh(gg);
                float o_ = fsig(go);
                int ci = i * 2 + j;
                float cn = f_ * creg[ci] + i_ * g_;
                creg[ci] = cn;
                float hv = o_ * ftanh(cn);
                hvreg[i][j] = hv;
                hn[(size_t)brow * HID + u] = __float2half_rn(hv);
            }
        }

        // arrive ASAP; prefetch next xw + archive hs while peers arrive; then wait
        int bi = gid * TSEQ + t;
        if (t < TSEQ - 1) {
            __threadfence();
            __syncthreads();
            if (tid == 0) atomicAdd(&bar[bi], 1);
            const __half* xwn = xw + (size_t)(t + 1) * BATCH * G4;
            #pragma unroll
            for (int i = 0; i < 2; i++)
                #pragma unroll
                for (int j = 0; j < 2; j++)
                    xg[i][j] = __ldg((const uint2*)(xwn + (size_t)erow[i] * G4 + 4 * (eu + 2 * j)));
        }
        #pragma unroll
        for (int i = 0; i < 2; i++)
            #pragma unroll
            for (int j = 0; j < 2; j++)
                hs[((size_t)erow[i] * TSEQ + t) * HID + eu + 2 * j] = __float2half_rn(hvreg[i][j]);
        if (t < TSEQ - 1) {
            if (tid == 0) { while (vbar[bi] < NGRP) {} }
            __syncthreads();
        }
    }
}

// ---------------- medium GEMM: C = A @ op(W) + bias, opt relu ------------------------
template <bool TRANS, bool RELU>
__global__ __launch_bounds__(256) void gemm_med(
    const float* __restrict__ A, const float* __restrict__ W,
    const float* __restrict__ bias, float* __restrict__ C,
    int M, int N, int K, int lda, int ldw, int ldc) {
    __shared__ float sA[16][68];
    __shared__ float sW[16][68];
    int m0 = blockIdx.y * 64, n0 = blockIdx.x * 64;
    int tid = threadIdx.x;
    int tx = tid & 15, ty = tid >> 4;
    float acc[4][4] = {};
    for (int k0 = 0; k0 < K; k0 += 16) {
        #pragma unroll
        for (int i = 0; i < 4; i++) {
            int idx = tid + i * 256;
            int r = idx >> 4, k = idx & 15;
            int mm = m0 + r, kk = k0 + k;
            sA[k][r] = (mm < M && kk < K) ? A[(size_t)mm * lda + kk] : 0.f;
            int nn = n0 + r;
            float v = 0.f;
            if (TRANS) { if (kk < K && nn < N) v = W[(size_t)kk * ldw + nn]; }
            else       { if (nn < N && kk < K) v = W[(size_t)nn * ldw + kk]; }
            sW[k][r] = v;
        }
        __syncthreads();
        #pragma unroll
        for (int k = 0; k < 16; k++) {
            float4 a = *(const float4*)&sA[k][ty * 4];
            float4 b = *(const float4*)&sW[k][tx * 4];
            acc[0][0] += a.x * b.x; acc[0][1] += a.x * b.y; acc[0][2] += a.x * b.z; acc[0][3] += a.x * b.w;
            acc[1][0] += a.y * b.x; acc[1][1] += a.y * b.y; acc[1][2] += a.y * b.z; acc[1][3] += a.y * b.w;
            acc[2][0] += a.z * b.x; acc[2][1] += a.z * b.y; acc[2][2] += a.z * b.z; acc[2][3] += a.z * b.w;
            acc[3][0] += a.w * b.x; acc[3][1] += a.w * b.y; acc[3][2] += a.w * b.z; acc[3][3] += a.w * b.w;
        }
        __syncthreads();
    }
    #pragma unroll
    for (int r = 0; r < 4; r++) {
        int m = m0 + ty * 4 + r;
        if (m >= M) continue;
        #pragma unroll
        for (int cc = 0; cc < 4; cc++) {
            int n = n0 + tx * 4 + cc;
            if (n >= N) continue;
            float v = acc[r][cc];
            if (bias) v += bias[n];
            if (RELU) v = fmaxf(v, 0.f);
            C[(size_t)m * ldc + n] = v;
        }
    }
}

// ---------------- tiny matvec ----------------
__global__ void matvec(const float* __restrict__ W, const float* __restrict__ x,
                       const float* __restrict__ bias, float* __restrict__ y,
                       int N, int K, int ldw) {
    int i = blockIdx.x * blockDim.x + threadIdx.x;
    if (i >= N) return;
    float a = bias ? bias[i] : 0.f;
    for (int k = 0; k < K; k++) a += W[(size_t)i * ldw + k] * x[k];
    y[i] = a;
}

// ---------------- fused attention over fp16 hs ---------------------------------------
__global__ void attn_kernel(const __half* __restrict__ hs, const float* __restrict__ qk,
                            float* __restrict__ hbar) {
    int b = blockIdx.x;
    __shared__ float sc[TSEQ];
    __shared__ float red[256];
    __shared__ float sqk[HID];
    int tid = threadIdx.x;
    int lane = tid & 31, w = tid >> 5;
    sqk[tid] = qk[b * HID + tid];
    __syncthreads();
    for (int t = w; t < TSEQ; t += 8) {
        const __half2* hrow = (const __half2*)(hs + ((size_t)b * TSEQ + t) * HID);
        float p = 0.f;
        #pragma unroll
        for (int j = 0; j < 4; j++) {
            int h2i = lane + 32 * j;
            float2 hv = __half22float2(hrow[h2i]);
            p += hv.x * sqk[2 * h2i] + hv.y * sqk[2 * h2i + 1];
        }
        #pragma unroll
        for (int o = 16; o > 0; o >>= 1) p += __shfl_down_sync(0xffffffffu, p, o);
        if (lane == 0) sc[t] = p;
    }
    __syncthreads();
    float scale = 1.0f / sqrtf((float)EDIM);
    float v = sc[tid] * scale;
    red[tid] = v; __syncthreads();
    for (int s = 128; s > 0; s >>= 1) { if (tid < s) red[tid] = fmaxf(red[tid], red[tid + s]); __syncthreads(); }
    float mx = red[0]; __syncthreads();
    float ev = expf(v - mx);
    red[tid] = ev; __syncthreads();
    for (int s = 128; s > 0; s >>= 1) { if (tid < s) red[tid] += red[tid + s]; __syncthreads(); }
    float sum = red[0]; __syncthreads();
    sc[tid] = ev / sum;
    __syncthreads();
    const __half* hb = hs + (size_t)b * TSEQ * HID;
    float acc = 0.f;
    for (int t = 0; t < TSEQ; t++) acc += sc[t] * __half2float(hb[(size_t)t * HID + tid]);
    hbar[b * HID + tid] = acc;
}

// ---------------- concat helpers ----------------
__global__ void sf_build(const __half* __restrict__ hs, const float* __restrict__ s,
                         float* __restrict__ sf) {
    int idx = blockIdx.x * blockDim.x + threadIdx.x;
    if (idx >= BATCH * EDIM) return;
    int b = idx / EDIM, j = idx % EDIM;
    sf[idx] = (j < HID) ? __half2float(hs[((size_t)b * TSEQ + (TSEQ - 1)) * HID + j])
                        : s[b * FDIM + (j - HID)];
}
// writes merged_state directly into merged[:, :DM] (stride NMERG)
__global__ void ms_build(const float* __restrict__ ao, const float* __restrict__ s,
                         float* __restrict__ merged) {
    int idx = blockIdx.x * blockDim.x + threadIdx.x;
    if (idx >= BATCH * DM) return;
    int b = idx / DM, j = idx % DM;
    merged[(size_t)b * NMERG + j] = (j < EDIM) ? ao[b * EDIM + j] : s[b * FDIM + (j - EDIM)];
}

// ---------------- 10-qubit VQC; reads merged[:, :40], writes merged[:, DM:DM+10] -----
struct c2f { float x, y; };
__device__ __forceinline__ c2f cmul(c2f a, c2f b) { return { a.x * b.x - a.y * b.y, a.x * b.y + a.y * b.x }; }
__device__ __forceinline__ c2f cadd(c2f a, c2f b) { return { a.x + b.x, a.y + b.y }; }
__device__ __forceinline__ void matmul2(c2f C[2][2], const c2f A[2][2], const c2f B[2][2]) {
    #pragma unroll
    for (int i = 0; i < 2; i++)
        #pragma unroll
        for (int j = 0; j < 2; j++)
            C[i][j] = cadd(cmul(A[i][0], B[0][j]), cmul(A[i][1], B[1][j]));
}

__global__ void vqc_kernel(float* __restrict__ merged, const float* __restrict__ qw) {
    int b = blockIdx.x;
    __shared__ c2f psi[1024];
    __shared__ float red[512];
    __shared__ float sang[40];
    int tid = threadIdx.x;
    const float PI_F = 3.14159265358979323846f;
    psi[tid] = { 0.03125f, 0.f };
    psi[tid + 512] = { 0.03125f, 0.f };
    if (tid < 40) sang[tid] = tanhf(merged[(size_t)b * NMERG + tid]) * PI_F;
    __syncthreads();

    for (int layer = 0; layer < 4; layer++) {
        for (int q = 0; q < 10; q++) {
            int idx = layer * 10 + q;
            float a = sang[idx];
            float w0 = qw[idx * 3 + 0], w1 = qw[idx * 3 + 1], w2 = qw[idx * 3 + 2];
            float ch, sh; sincosf(0.5f * a, &sh, &ch);
            c2f Rx[2][2] = { { {ch, 0.f}, {0.f, -sh} }, { {0.f, -sh}, {ch, 0.f} } };
            c2f Rya[2][2] = { { {ch, 0.f}, {-sh, 0.f} }, { {sh, 0.f}, {ch, 0.f} } };
            c2f T1[2][2]; matmul2(T1, Rya, Rx);
            float c0, s0; sincosf(0.5f * w0, &s0, &c0);
            c2f Rz0[2][2] = { { {c0, -s0}, {0.f, 0.f} }, { {0.f, 0.f}, {c0, s0} } };
            c2f T2[2][2]; matmul2(T2, Rz0, T1);
            float c1, s1; sincosf(0.5f * w1, &s1, &c1);
            c2f Ry1[2][2] = { { {c1, 0.f}, {-s1, 0.f} }, { {s1, 0.f}, {c1, 0.f} } };
            c2f T3[2][2]; matmul2(T3, Ry1, T2);
            float c2r, s2r; sincosf(0.5f * w2, &s2r, &c2r);
            c2f Rz2[2][2] = { { {c2r, -s2r}, {0.f, 0.f} }, { {0.f, 0.f}, {c2r, s2r} } };
            c2f U[2][2]; matmul2(U, Rz2, T3);

            int bq = 9 - q;
            int low = tid & ((1 << bq) - 1);
            int i0 = ((tid >> bq) << (bq + 1)) | low;
            int i1 = i0 | (1 << bq);
            __syncthreads();
            c2f a0 = psi[i0], a1 = psi[i1];
            psi[i0] = cadd(cmul(U[0][0], a0), cmul(U[0][1], a1));
            psi[i1] = cadd(cmul(U[1][0], a0), cmul(U[1][1], a1));
        }
        for (int qq = 0; qq < 10; qq++) {
            int ctrl = (qq < 9) ? qq : 9;
            int tgt  = (qq < 9) ? qq + 1 : 0;
            int bc = 9 - ctrl, bt = 9 - tgt;
            __syncthreads();
            if (tid < 256) {
                int lo = min(bc, bt), hi = max(bc, bt);
                int i = tid;
                i = ((i >> lo) << (lo + 1)) | (i & ((1 << lo) - 1));
                i = ((i >> hi) << (hi + 1)) | (i & ((1 << hi) - 1));
                i |= (1 << bc);
                int j0 = i;
                int j1 = i | (1 << bt);
                c2f tmp = psi[j0]; psi[j0] = psi[j1]; psi[j1] = tmp;
            }
        }
    }
    __syncthreads();
    c2f p0 = psi[tid], p1 = psi[tid + 512];
    float n0 = p0.x * p0.x + p0.y * p0.y;
    float n1 = p1.x * p1.x + p1.y * p1.y;
    for (int k = 0; k < 10; k++) {
        int bp = 9 - k;
        float s0v = ((tid >> bp) & 1) ? -n0 : n0;
        float s1v = (((tid + 512) >> bp) & 1) ? -n1 : n1;
        red[tid] = s0v + s1v;
        __syncthreads();
        for (int s = 256; s > 0; s >>= 1) { if (tid < s) red[tid] += red[tid + s]; __syncthreads(); }
        if (tid == 0) merged[(size_t)b * NMERG + DM + k] = red[0];
        __syncthreads();
    }
}

// ---------------- host launch ----------------
#define GETSYM(p, sym) do { void* _t = nullptr; cudaGetSymbolAddress(&_t, sym); (p) = (float*)_t; } while (0)

extern "C" void kernel_launch(void* const* d_in, const int* in_sizes, int n_in,
                              void* d_out, int out_size) {
    const float* s          = (const float*)d_in[0];
    const float* lstm_s     = (const float*)d_in[1];
    const float* W_ih       = (const float*)d_in[2];
    const float* W_hh       = (const float*)d_in[3];
    const float* b_ih       = (const float*)d_in[4];
    const float* b_hh       = (const float*)d_in[5];
    const float* proj_W     = (const float*)d_in[6];
    const float* proj_b     = (const float*)d_in[7];
    const float* in_proj_W  = (const float*)d_in[8];
    const float* in_proj_b  = (const float*)d_in[9];
    const float* out_proj_W = (const float*)d_in[10];
    const float* out_proj_b = (const float*)d_in[11];
    const float* qweights   = (const float*)d_in[12];
    const float* W1         = (const float*)d_in[13];
    const float* b1         = (const float*)d_in[14];
    const float* W2         = (const float*)d_in[15];
    const float* b2         = (const float*)d_in[16];
    float* out = (float*)d_out;

    float *Wip, *Wp, *bp, *sf, *qv, *qk, *Mkp, *MA1, *Amat;
    float *vconst, *aconst, *hbar, *ao, *merged, *x1;
    __half *xw, *hbuf, *hs;
    int* bar;
    { void* _t = nullptr; cudaGetSymbolAddress(&_t, d_xw); xw = (__half*)_t; }
    { void* _t = nullptr; cudaGetSymbolAddress(&_t, d_hbuf); hbuf = (__half*)_t; }
    { void* _t = nullptr; cudaGetSymbolAddress(&_t, d_hs); hs = (__half*)_t; }
    GETSYM(Wip, d_Wip); GETSYM(Wp, d_Wp);   GETSYM(bp, d_bp);   GETSYM(sf, d_sf);
    GETSYM(qv, d_q);    GETSYM(qk, d_qk);   GETSYM(Mkp, d_Mkp); GETSYM(MA1, d_MA1);
    GETSYM(Amat, d_Amat); GETSYM(vconst, d_vconst); GETSYM(aconst, d_aconst);
    GETSYM(hbar, d_hbar); GETSYM(ao, d_ao);
    GETSYM(merged, d_merged); GETSYM(x1, d_x1);
    { void* _t = nullptr; cudaGetSymbolAddress(&_t, d_bar); bar = (int*)_t; }

    const float* Wq = in_proj_W;
    const float* Wk = in_proj_W + EDIM * EDIM;
    const float* Wv = in_proj_W + 2 * EDIM * EDIM;
    const float* bq = in_proj_b;
    const float* bv = in_proj_b + 2 * EDIM;

    cudaMemsetAsync(bar, 0, 16 * TSEQ * sizeof(int));

    // weight permutation (gate-interleaved)
    permute_kernel<<<G4, 128>>>(W_ih, W_hh, b_ih, b_hh, Wip, Wp, bp);

    // big input GEMM (fp16 tensor cores): xw[t,b,:] = X @ Wip^T + bp (fp16 out)
    xw_gemm_f16<<<dim3(G4 / 128, (BATCH * TSEQ) / 128), 256>>>(lstm_s, Wip, bp, xw);

    // persistent LSTM recurrence (16 groups x 8 blocks, xw prefetch)
    lstm_persist<<<NBLK, 256>>>(xw, Wp, hs, hbuf, bar);

    // state_full = [h_last, s]; q = sf @ Wq^T + bq
    sf_build<<<(BATCH * EDIM + 255) / 256, 256>>>(hs, s, sf);
    gemm_med<false, false><<<dim3(5, 8), 256>>>(sf, Wq, bq, qv, BATCH, EDIM, EDIM, EDIM, EDIM, EDIM);

    // precompose attention matrices
    gemm_med<true, false><<<dim3(4, 5), 256>>>(Wk, proj_W, nullptr, Mkp, EDIM, HID, EDIM, EDIM, HID, HID);
    gemm_med<true, false><<<dim3(4, 8), 256>>>(qv, Mkp, nullptr, qk, BATCH, HID, EDIM, EDIM, HID, HID);
    gemm_med<true, false><<<dim3(4, 5), 256>>>(Wv, proj_W, nullptr, MA1, EDIM, HID, EDIM, EDIM, HID, HID);
    gemm_med<true, false><<<dim3(4, 5), 256>>>(out_proj_W, MA1, nullptr, Amat, EDIM, HID, EDIM, EDIM, HID, HID);
    matvec<<<1, EDIM>>>(Wv, proj_b, bv, vconst, EDIM, EDIM, EDIM);
    matvec<<<1, EDIM>>>(out_proj_W, vconst, out_proj_b, aconst, EDIM, EDIM, EDIM);

    // fused attention over hs
    attn_kernel<<<BATCH, 256>>>(hs, qk, hbar);

    // attn_out = hbar @ Amat^T + aconst; merged[:, :DM] = [attn_out, s]
    gemm_med<false, false><<<dim3(5, 8), 256>>>(hbar, Amat, aconst, ao, BATCH, EDIM, HID, HID, HID, EDIM);
    ms_build<<<(BATCH * DM + 255) / 256, 256>>>(ao, s, merged);

    // VQC (writes qfeat into merged[:, DM:])
    vqc_kernel<<<BATCH, 512>>>(merged, qweights);

    // MLP (reads merged directly, lda = NMERG)
    gemm_med<false, true><<<dim3(8, 8), 256>>>(merged, W1, b1, x1, BATCH, NL1, NMERG, NMERG, NMERG, NL1);
    gemm_med<false, false><<<dim3(1, 8), 256>>>(x1, W2, b2, out, BATCH, NACT, NL1, NL1, NL1, NACT);
}

// round 11
// speedup vs baseline: 1.4486x; 1.0538x over previous
#include <cuda_runtime.h>
#include <cuda_fp16.h>
#include <math.h>
#include <stdint.h>

#define BATCH 512
#define TSEQ  256
#define DIN   128
#define HID   256
#define G4    1024
#define FDIM  64
#define EDIM  320
#define DM    384
#define NMERG 394
#define NL1   512
#define NACT  8

#define NBLK   128   // persistent grid: 16 batch-groups x 8 col-tiles
#define NGRP   8     // blocks per batch-group barrier

// ---------------- scratch (static device memory; no allocations) ----------------
__device__ __half d_hs[33554432];      // [B, T, H] fp16 hidden states
__device__ __half d_hbuf[2 * BATCH * HID]; // double-buffered compact h (fp16)
__device__ int   d_bar[16 * TSEQ];     // per (batch-group, step) barrier counters
__device__ float d_Wip[G4 * DIN];      // permuted W_ih
__device__ float d_Wp[G4 * HID];       // permuted W_hh
__device__ float d_bp[G4];             // permuted bias
__device__ float d_sf[BATCH * EDIM];   // state_full
__device__ float d_q[BATCH * EDIM];
__device__ float d_qk[BATCH * HID];
__device__ float d_Mkp[EDIM * HID];    // Wk @ proj_W
__device__ float d_MA1[EDIM * HID];    // Wv @ proj_W
__device__ float d_Amat[EDIM * HID];   // Wo @ Wv @ proj_W
__device__ float d_vconst[EDIM];
__device__ float d_aconst[EDIM];
__device__ float d_hbar[BATCH * HID];
__device__ float d_ao[BATCH * EDIM];
__device__ float d_merged[BATCH * NMERG];  // [merged_state | qfeat]
__device__ float d_x1[BATCH * NL1];

// ---------------- fp16 mma helpers ----------------
__device__ __forceinline__ uint32_t pack_h2(float x, float y) {
    __half2 t = __floats2half2_rn(x, y);
    return *reinterpret_cast<uint32_t*>(&t);
}
__device__ __forceinline__ void mma_f16(float* c, uint32_t a0, uint32_t a1,
                                        uint32_t a2, uint32_t a3,
                                        uint32_t b0, uint32_t b1) {
    asm volatile("mma.sync.aligned.m16n8k16.row.col.f32.f16.f16.f32 "
        "{%0,%1,%2,%3}, {%4,%5,%6,%7}, {%8,%9}, {%0,%1,%2,%3};"
        : "+f"(c[0]), "+f"(c[1]), "+f"(c[2]), "+f"(c[3])
        : "r"(a0), "r"(a1), "r"(a2), "r"(a3), "r"(b0), "r"(b1));
}
__device__ __forceinline__ float fsig(float x) {
    return __fdividef(1.f, 1.f + __expf(-x));
}
__device__ __forceinline__ float ftanh(float x) {
    return 2.f * fsig(2.f * x) - 1.f;
}

// ---------------- weight permutation: column 4u+g = gate g of unit u ----------------
__global__ void permute_kernel(const float* __restrict__ W_ih, const float* __restrict__ W_hh,
                               const float* __restrict__ b_ih, const float* __restrict__ b_hh,
                               float* __restrict__ Wip, float* __restrict__ Wp, float* __restrict__ bp) {
    int n = blockIdx.x;            // 0..1023, permuted row
    int u = n >> 2, g = n & 3;
    int o = g * HID + u;           // original row
    for (int k = threadIdx.x; k < DIN; k += blockDim.x) Wip[n * DIN + k] = W_ih[o * DIN + k];
    for (int k = threadIdx.x; k < HID; k += blockDim.x) Wp[n * HID + k] = W_hh[o * HID + k];
    if (threadIdx.x == 0) bp[n] = b_ih[o] + b_hh[o];
}

// ---------------- persistent fused LSTM: gates = x_t@Wip^T + h@Wp^T + bp -------------
// 128 blocks: 16 batch-groups (32 rows) x 8 col-tiles (128 gate cols). 8 warps,
// warp tile m32 x n16 via m16n8k16. Wip+Wp fragments register-resident. x tile
// loaded into smem during the barrier spin (independent of h). No xw tensor.
__global__ __launch_bounds__(256, 1) void lstm_persist(
    const float* __restrict__ X, const float* __restrict__ Wip,
    const float* __restrict__ Wp, const float* __restrict__ bp,
    __half* __restrict__ hs, __half* __restrict__ hbuf, int* __restrict__ bar)
{
    __shared__ __half sA[32][264];   // h tile [32 rows][256 + pad]
    __shared__ __half sX[32][136];   // x tile [32 rows][128 + pad]
    int bx = blockIdx.x & 7;        // col tile (128 cols)
    int gid = blockIdx.x >> 3;      // batch group (0..15, 32 rows)
    int n0 = bx * 128, m0 = gid * 32;
    int tid = threadIdx.x;
    int wid = tid >> 5, lane = tid & 31;
    int g = lane >> 2, t4 = lane & 3;
    int warp_n = wid * 16;
    int odd = lane & 1;

    // ---- preload B fragments: Wp (k16 x 16 ksteps) and Wip (k16 x 8 ksteps) ----
    uint32_t bregh[2][16][2];
    uint32_t bregx[2][8][2];
    #pragma unroll
    for (int j = 0; j < 2; j++) {
        int col = n0 + warp_n + 8 * j + g;
        const float* wrow = Wp + (size_t)col * HID;
        #pragma unroll
        for (int kk = 0; kk < 16; kk++) {
            bregh[j][kk][0] = pack_h2(__ldg(wrow + kk * 16 + 2 * t4),
                                      __ldg(wrow + kk * 16 + 2 * t4 + 1));
            bregh[j][kk][1] = pack_h2(__ldg(wrow + kk * 16 + 2 * t4 + 8),
                                      __ldg(wrow + kk * 16 + 2 * t4 + 9));
        }
        const float* xrow = Wip + (size_t)col * DIN;
        #pragma unroll
        for (int kk = 0; kk < 8; kk++) {
            bregx[j][kk][0] = pack_h2(__ldg(xrow + kk * 16 + 2 * t4),
                                      __ldg(xrow + kk * 16 + 2 * t4 + 1));
            bregx[j][kk][1] = pack_h2(__ldg(xrow + kk * 16 + 2 * t4 + 8),
                                      __ldg(xrow + kk * 16 + 2 * t4 + 9));
        }
    }
    float creg[4] = {0.f, 0.f, 0.f, 0.f};
    volatile int* vbar = bar;

    // epilogue row/unit coords + bias registers
    int erow[2], eu;
    erow[0] = m0 + g + (odd ? 8 : 0);
    erow[1] = erow[0] + 16;
    eu = ((n0 + warp_n) >> 2) + ((lane >> 1) & 1);
    float4 bb[2];
    #pragma unroll
    for (int j = 0; j < 2; j++) bb[j] = *(const float4*)(bp + 4 * (eu + 2 * j));

    // preload x tile for t=0
    #pragma unroll
    for (int itr = 0; itr < 4; itr++) {
        int gi = itr * 256 + tid;
        int row = gi >> 5;          // 0..31
        int c4 = gi & 31;           // float4 within 128 floats
        float4 v = __ldg((const float4*)(X + ((size_t)(m0 + row) * TSEQ + 0) * DIN + c4 * 4));
        uint2 pk = { pack_h2(v.x, v.y), pack_h2(v.z, v.w) };
        *(uint2*)&sX[row][c4 * 4] = pk;
    }
    __syncthreads();

    for (int t = 0; t < TSEQ; t++) {
        float c[2][2][4];
        #pragma unroll
        for (int i = 0; i < 2; i++)
            #pragma unroll
            for (int j = 0; j < 2; j++)
                #pragma unroll
                for (int e = 0; e < 4; e++) c[i][j][e] = 0.f;

        if (t > 0) {
            const __half* hp = hbuf + (size_t)(t & 1) * (BATCH * HID);
            // fill h tile: 32 rows x 256 halves = 16 KB
            #pragma unroll
            for (int itr = 0; itr < 4; itr++) {
                int gi = itr * 256 + tid;
                int row = gi >> 5;
                int s2 = gi & 31;
                uint4 v = __ldcg((const uint4*)(hp + (size_t)(m0 + row) * HID + s2 * 8));
                *(uint4*)&sA[row][s2 * 8] = v;
            }
            __syncthreads();
            // h-part: 16 k-steps
            #pragma unroll
            for (int kk = 0; kk < 16; kk++) {
                #pragma unroll
                for (int i = 0; i < 2; i++) {
                    int r0 = 16 * i + g;
                    const __half* alo = &sA[r0][kk * 16 + 2 * t4];
                    const __half* ahi = &sA[r0 + 8][kk * 16 + 2 * t4];
                    uint32_t a0 = *(const uint32_t*)alo;
                    uint32_t a2 = *(const uint32_t*)(alo + 8);
                    uint32_t a1 = *(const uint32_t*)ahi;
                    uint32_t a3 = *(const uint32_t*)(ahi + 8);
                    mma_f16(c[i][0], a0, a1, a2, a3, bregh[0][kk][0], bregh[0][kk][1]);
                    mma_f16(c[i][1], a0, a1, a2, a3, bregh[1][kk][0], bregh[1][kk][1]);
                }
            }
        }
        // x-part: 8 k-steps (sX holds x_t, loaded during previous spin)
        #pragma unroll
        for (int kk = 0; kk < 8; kk++) {
            #pragma unroll
            for (int i = 0; i < 2; i++) {
                int r0 = 16 * i + g;
                const __half* alo = &sX[r0][kk * 16 + 2 * t4];
                const __half* ahi = &sX[r0 + 8][kk * 16 + 2 * t4];
                uint32_t a0 = *(const uint32_t*)alo;
                uint32_t a2 = *(const uint32_t*)(alo + 8);
                uint32_t a1 = *(const uint32_t*)ahi;
                uint32_t a3 = *(const uint32_t*)(ahi + 8);
                mma_f16(c[i][0], a0, a1, a2, a3, bregx[0][kk][0], bregx[0][kk][1]);
                mma_f16(c[i][1], a0, a1, a2, a3, bregx[1][kk][0], bregx[1][kk][1]);
            }
        }

        // ---- epilogue: gate exchange via shfl, cell update (bias in regs) ----
        __half* hn = hbuf + (size_t)((t + 1) & 1) * (BATCH * HID);
        float hvreg[2][2];
        #pragma unroll
        for (int i = 0; i < 2; i++) {
            #pragma unroll
            for (int j = 0; j < 2; j++) {
                float u0 = odd ? c[i][j][0] : c[i][j][2];
                float u1 = odd ? c[i][j][1] : c[i][j][3];
                float rx0 = __shfl_xor_sync(0xffffffffu, u0, 1);
                float rx1 = __shfl_xor_sync(0xffffffffu, u1, 1);
                float gi, gf, gg, go;
                if (!odd) { gi = c[i][j][0]; gf = c[i][j][1]; gg = rx0; go = rx1; }
                else      { gi = rx0; gf = rx1; gg = c[i][j][2]; go = c[i][j][3]; }
                gi += bb[j].x; gf += bb[j].y; gg += bb[j].z; go += bb[j].w;
                int brow = erow[i];
                int u = eu + 2 * j;
                float i_ = fsig(gi);
                float f_ = fsig(gf);
                float g_ = ftanh(gg);
                float o_ = fsig(go);
                int ci = i * 2 + j;
                float cn = f_ * creg[ci] + i_ * g_;
                creg[ci] = cn;
                float hv = o_ * ftanh(cn);
                hvreg[i][j] = hv;
                hn[(size_t)brow * HID + u] = __float2half_rn(hv);
            }
        }

        // arrive ASAP; load x[t+1] + archive hs while peers arrive; then wait
        int bi = gid * TSEQ + t;
        if (t < TSEQ - 1) {
            __threadfence();
            __syncthreads();
            if (tid == 0) atomicAdd(&bar[bi], 1);
            // load next step's x tile (independent of peers; DRAM latency hides)
            #pragma unroll
            for (int itr = 0; itr < 4; itr++) {
                int gi = itr * 256 + tid;
                int row = gi >> 5;
                int c4 = gi & 31;
                float4 v = __ldg((const float4*)(X + ((size_t)(m0 + row) * TSEQ + (t + 1)) * DIN + c4 * 4));
                uint2 pk = { pack_h2(v.x, v.y), pack_h2(v.z, v.w) };
                *(uint2*)&sX[row][c4 * 4] = pk;
            }
        }
        #pragma unroll
        for (int i = 0; i < 2; i++)
            #pragma unroll
            for (int j = 0; j < 2; j++)
                hs[((size_t)erow[i] * TSEQ + t) * HID + eu + 2 * j] = __float2half_rn(hvreg[i][j]);
        if (t < TSEQ - 1) {
            if (tid == 0) { while (vbar[bi] < NGRP) {} }
            __syncthreads();
        }
    }
}

// ---------------- medium GEMM: C = A @ op(W) + bias, opt relu ------------------------
template <bool TRANS, bool RELU>
__global__ __launch_bounds__(256) void gemm_med(
    const float* __restrict__ A, const float* __restrict__ W,
    const float* __restrict__ bias, float* __restrict__ C,
    int M, int N, int K, int lda, int ldw, int ldc) {
    __shared__ float sA[16][68];
    __shared__ float sW[16][68];
    int m0 = blockIdx.y * 64, n0 = blockIdx.x * 64;
    int tid = threadIdx.x;
    int tx = tid & 15, ty = tid >> 4;
    float acc[4][4] = {};
    for (int k0 = 0; k0 < K; k0 += 16) {
        #pragma unroll
        for (int i = 0; i < 4; i++) {
            int idx = tid + i * 256;
            int r = idx >> 4, k = idx & 15;
            int mm = m0 + r, kk = k0 + k;
            sA[k][r] = (mm < M && kk < K) ? A[(size_t)mm * lda + kk] : 0.f;
            int nn = n0 + r;
            float v = 0.f;
            if (TRANS) { if (kk < K && nn < N) v = W[(size_t)kk * ldw + nn]; }
            else       { if (nn < N && kk < K) v = W[(size_t)nn * ldw + kk]; }
            sW[k][r] = v;
        }
        __syncthreads();
        #pragma unroll
        for (int k = 0; k < 16; k++) {
            float4 a = *(const float4*)&sA[k][ty * 4];
            float4 b = *(const float4*)&sW[k][tx * 4];
            acc[0][0] += a.x * b.x; acc[0][1] += a.x * b.y; acc[0][2] += a.x * b.z; acc[0][3] += a.x * b.w;
            acc[1][0] += a.y * b.x; acc[1][1] += a.y * b.y; acc[1][2] += a.y * b.z; acc[1][3] += a.y * b.w;
            acc[2][0] += a.z * b.x; acc[2][1] += a.z * b.y; acc[2][2] += a.z * b.z; acc[2][3] += a.z * b.w;
            acc[3][0] += a.w * b.x; acc[3][1] += a.w * b.y; acc[3][2] += a.w * b.z; acc[3][3] += a.w * b.w;
        }
        __syncthreads();
    }
    #pragma unroll
    for (int r = 0; r < 4; r++) {
        int m = m0 + ty * 4 + r;
        if (m >= M) continue;
        #pragma unroll
        for (int cc = 0; cc < 4; cc++) {
            int n = n0 + tx * 4 + cc;
            if (n >= N) continue;
            float v = acc[r][cc];
            if (bias) v += bias[n];
            if (RELU) v = fmaxf(v, 0.f);
            C[(size_t)m * ldc + n] = v;
        }
    }
}

// ---------------- tiny matvec ----------------
__global__ void matvec(const float* __restrict__ W, const float* __restrict__ x,
                       const float* __restrict__ bias, float* __restrict__ y,
                       int N, int K, int ldw) {
    int i = blockIdx.x * blockDim.x + threadIdx.x;
    if (i >= N) return;
    float a = bias ? bias[i] : 0.f;
    for (int k = 0; k < K; k++) a += W[(size_t)i * ldw + k] * x[k];
    y[i] = a;
}

// ---------------- fused attention over fp16 hs ---------------------------------------
__global__ void attn_kernel(const __half* __restrict__ hs, const float* __restrict__ qk,
                            float* __restrict__ hbar) {
    int b = blockIdx.x;
    __shared__ float sc[TSEQ];
    __shared__ float red[256];
    __shared__ float sqk[HID];
    int tid = threadIdx.x;
    int lane = tid & 31, w = tid >> 5;
    sqk[tid] = qk[b * HID + tid];
    __syncthreads();
    for (int t = w; t < TSEQ; t += 8) {
        const __half2* hrow = (const __half2*)(hs + ((size_t)b * TSEQ + t) * HID);
        float p = 0.f;
        #pragma unroll
        for (int j = 0; j < 4; j++) {
            int h2i = lane + 32 * j;
            float2 hv = __half22float2(hrow[h2i]);
            p += hv.x * sqk[2 * h2i] + hv.y * sqk[2 * h2i + 1];
        }
        #pragma unroll
        for (int o = 16; o > 0; o >>= 1) p += __shfl_down_sync(0xffffffffu, p, o);
        if (lane == 0) sc[t] = p;
    }
    __syncthreads();
    float scale = 1.0f / sqrtf((float)EDIM);
    float v = sc[tid] * scale;
    red[tid] = v; __syncthreads();
    for (int s = 128; s > 0; s >>= 1) { if (tid < s) red[tid] = fmaxf(red[tid], red[tid + s]); __syncthreads(); }
    float mx = red[0]; __syncthreads();
    float ev = expf(v - mx);
    red[tid] = ev; __syncthreads();
    for (int s = 128; s > 0; s >>= 1) { if (tid < s) red[tid] += red[tid + s]; __syncthreads(); }
    float sum = red[0]; __syncthreads();
    sc[tid] = ev / sum;
    __syncthreads();
    const __half* hb = hs + (size_t)b * TSEQ * HID;
    float acc = 0.f;
    for (int t = 0; t < TSEQ; t++) acc += sc[t] * __half2float(hb[(size_t)t * HID + tid]);
    hbar[b * HID + tid] = acc;
}

// ---------------- concat helpers ----------------
__global__ void sf_build(const __half* __restrict__ hs, const float* __restrict__ s,
                         float* __restrict__ sf) {
    int idx = blockIdx.x * blockDim.x + threadIdx.x;
    if (idx >= BATCH * EDIM) return;
    int b = idx / EDIM, j = idx % EDIM;
    sf[idx] = (j < HID) ? __half2float(hs[((size_t)b * TSEQ + (TSEQ - 1)) * HID + j])
                        : s[b * FDIM + (j - HID)];
}
// writes merged_state directly into merged[:, :DM] (stride NMERG)
__global__ void ms_build(const float* __restrict__ ao, const float* __restrict__ s,
                         float* __restrict__ merged) {
    int idx = blockIdx.x * blockDim.x + threadIdx.x;
    if (idx >= BATCH * DM) return;
    int b = idx / DM, j = idx % DM;
    merged[(size_t)b * NMERG + j] = (j < EDIM) ? ao[b * EDIM + j] : s[b * FDIM + (j - EDIM)];
}

// ---------------- 10-qubit VQC; reads merged[:, :40], writes merged[:, DM:DM+10] -----
struct c2f { float x, y; };
__device__ __forceinline__ c2f cmul(c2f a, c2f b) { return { a.x * b.x - a.y * b.y, a.x * b.y + a.y * b.x }; }
__device__ __forceinline__ c2f cadd(c2f a, c2f b) { return { a.x + b.x, a.y + b.y }; }
__device__ __forceinline__ void matmul2(c2f C[2][2], const c2f A[2][2], const c2f B[2][2]) {
    #pragma unroll
    for (int i = 0; i < 2; i++)
        #pragma unroll
        for (int j = 0; j < 2; j++)
            C[i][j] = cadd(cmul(A[i][0], B[0][j]), cmul(A[i][1], B[1][j]));
}

__global__ void vqc_kernel(float* __restrict__ merged, const float* __restrict__ qw) {
    int b = blockIdx.x;
    __shared__ c2f psi[1024];
    __shared__ float red[512];
    __shared__ float sang[40];
    int tid = threadIdx.x;
    const float PI_F = 3.14159265358979323846f;
    psi[tid] = { 0.03125f, 0.f };
    psi[tid + 512] = { 0.03125f, 0.f };
    if (tid < 40) sang[tid] = tanhf(merged[(size_t)b * NMERG + tid]) * PI_F;
    __syncthreads();

    for (int layer = 0; layer < 4; layer++) {
        for (int q = 0; q < 10; q++) {
            int idx = layer * 10 + q;
            float a = sang[idx];
            float w0 = qw[idx * 3 + 0], w1 = qw[idx * 3 + 1], w2 = qw[idx * 3 + 2];
            float ch, sh; sincosf(0.5f * a, &sh, &ch);
            c2f Rx[2][2] = { { {ch, 0.f}, {0.f, -sh} }, { {0.f, -sh}, {ch, 0.f} } };
            c2f Rya[2][2] = { { {ch, 0.f}, {-sh, 0.f} }, { {sh, 0.f}, {ch, 0.f} } };
            c2f T1[2][2]; matmul2(T1, Rya, Rx);
            float c0, s0; sincosf(0.5f * w0, &s0, &c0);
            c2f Rz0[2][2] = { { {c0, -s0}, {0.f, 0.f} }, { {0.f, 0.f}, {c0, s0} } };
            c2f T2[2][2]; matmul2(T2, Rz0, T1);
            float c1, s1; sincosf(0.5f * w1, &s1, &c1);
            c2f Ry1[2][2] = { { {c1, 0.f}, {-s1, 0.f} }, { {s1, 0.f}, {c1, 0.f} } };
            c2f T3[2][2]; matmul2(T3, Ry1, T2);
            float c2r, s2r; sincosf(0.5f * w2, &s2r, &c2r);
            c2f Rz2[2][2] = { { {c2r, -s2r}, {0.f, 0.f} }, { {0.f, 0.f}, {c2r, s2r} } };
            c2f U[2][2]; matmul2(U, Rz2, T3);

            int bq = 9 - q;
            int low = tid & ((1 << bq) - 1);
            int i0 = ((tid >> bq) << (bq + 1)) | low;
            int i1 = i0 | (1 << bq);
            __syncthreads();
            c2f a0 = psi[i0], a1 = psi[i1];
            psi[i0] = cadd(cmul(U[0][0], a0), cmul(U[0][1], a1));
            psi[i1] = cadd(cmul(U[1][0], a0), cmul(U[1][1], a1));
        }
        for (int qq = 0; qq < 10; qq++) {
            int ctrl = (qq < 9) ? qq : 9;
            int tgt  = (qq < 9) ? qq + 1 : 0;
            int bc = 9 - ctrl, bt = 9 - tgt;
            __syncthreads();
            if (tid < 256) {
                int lo = min(bc, bt), hi = max(bc, bt);
                int i = tid;
                i = ((i >> lo) << (lo + 1)) | (i & ((1 << lo) - 1));
                i = ((i >> hi) << (hi + 1)) | (i & ((1 << hi) - 1));
                i |= (1 << bc);
                int j0 = i;
                int j1 = i | (1 << bt);
                c2f tmp = psi[j0]; psi[j0] = psi[j1]; psi[j1] = tmp;
            }
        }
    }
    __syncthreads();
    c2f p0 = psi[tid], p1 = psi[tid + 512];
    float n0 = p0.x * p0.x + p0.y * p0.y;
    float n1 = p1.x * p1.x + p1.y * p1.y;
    for (int k = 0; k < 10; k++) {
        int bp_ = 9 - k;
        float s0v = ((tid >> bp_) & 1) ? -n0 : n0;
        float s1v = (((tid + 512) >> bp_) & 1) ? -n1 : n1;
        red[tid] = s0v + s1v;
        __syncthreads();
        for (int s = 256; s > 0; s >>= 1) { if (tid < s) red[tid] += red[tid + s]; __syncthreads(); }
        if (tid == 0) merged[(size_t)b * NMERG + DM + k] = red[0];
        __syncthreads();
    }
}

// ---------------- host launch ----------------
#define GETSYM(p, sym) do { void* _t = nullptr; cudaGetSymbolAddress(&_t, sym); (p) = (float*)_t; } while (0)

extern "C" void kernel_launch(void* const* d_in, const int* in_sizes, int n_in,
                              void* d_out, int out_size) {
    const float* s          = (const float*)d_in[0];
    const float* lstm_s     = (const float*)d_in[1];
    const float* W_ih       = (const float*)d_in[2];
    const float* W_hh       = (const float*)d_in[3];
    const float* b_ih       = (const float*)d_in[4];
    const float* b_hh       = (const float*)d_in[5];
    const float* proj_W     = (const float*)d_in[6];
    const float* proj_b     = (const float*)d_in[7];
    const float* in_proj_W  = (const float*)d_in[8];
    const float* in_proj_b  = (const float*)d_in[9];
    const float* out_proj_W = (const float*)d_in[10];
    const float* out_proj_b = (const float*)d_in[11];
    const float* qweights   = (const float*)d_in[12];
    const float* W1         = (const float*)d_in[13];
    const float* b1         = (const float*)d_in[14];
    const float* W2         = (const float*)d_in[15];
    const float* b2         = (const float*)d_in[16];
    float* out = (float*)d_out;

    float *Wip, *Wp, *bp, *sf, *qv, *qk, *Mkp, *MA1, *Amat;
    float *vconst, *aconst, *hbar, *ao, *merged, *x1;
    __half *hbuf, *hs;
    int* bar;
    { void* _t = nullptr; cudaGetSymbolAddress(&_t, d_hbuf); hbuf = (__half*)_t; }
    { void* _t = nullptr; cudaGetSymbolAddress(&_t, d_hs); hs = (__half*)_t; }
    GETSYM(Wip, d_Wip); GETSYM(Wp, d_Wp);   GETSYM(bp, d_bp);   GETSYM(sf, d_sf);
    GETSYM(qv, d_q);    GETSYM(qk, d_qk);   GETSYM(Mkp, d_Mkp); GETSYM(MA1, d_MA1);
    GETSYM(Amat, d_Amat); GETSYM(vconst, d_vconst); GETSYM(aconst, d_aconst);
    GETSYM(hbar, d_hbar); GETSYM(ao, d_ao);
    GETSYM(merged, d_merged); GETSYM(x1, d_x1);
    { void* _t = nullptr; cudaGetSymbolAddress(&_t, d_bar); bar = (int*)_t; }

    const float* Wq = in_proj_W;
    const float* Wk = in_proj_W + EDIM * EDIM;
    const float* Wv = in_proj_W + 2 * EDIM * EDIM;
    const float* bq = in_proj_b;
    const float* bv = in_proj_b + 2 * EDIM;

    cudaMemsetAsync(bar, 0, 16 * TSEQ * sizeof(int));

    // weight permutation (gate-interleaved)
    permute_kernel<<<G4, 128>>>(W_ih, W_hh, b_ih, b_hh, Wip, Wp, bp);

    // persistent fused LSTM (input GEMM + recurrence in one kernel)
    lstm_persist<<<NBLK, 256>>>(lstm_s, Wip, Wp, bp, hs, hbuf, bar);

    // state_full = [h_last, s]; q = sf @ Wq^T + bq
    sf_build<<<(BATCH * EDIM + 255) / 256, 256>>>(hs, s, sf);
    gemm_med<false, false><<<dim3(5, 8), 256>>>(sf, Wq, bq, qv, BATCH, EDIM, EDIM, EDIM, EDIM, EDIM);

    // precompose attention matrices
    gemm_med<true, false><<<dim3(4, 5), 256>>>(Wk, proj_W, nullptr, Mkp, EDIM, HID, EDIM, EDIM, HID, HID);
    gemm_med<true, false><<<dim3(4, 8), 256>>>(qv, Mkp, nullptr, qk, BATCH, HID, EDIM, EDIM, HID, HID);
    gemm_med<true, false><<<dim3(4, 5), 256>>>(Wv, proj_W, nullptr, MA1, EDIM, HID, EDIM, EDIM, HID, HID);
    gemm_med<true, false><<<dim3(4, 5), 256>>>(out_proj_W, MA1, nullptr, Amat, EDIM, HID, EDIM, EDIM, HID, HID);
    matvec<<<1, EDIM>>>(Wv, proj_b, bv, vconst, EDIM, EDIM, EDIM);
    matvec<<<1, EDIM>>>(out_proj_W, vconst, out_proj_b, aconst, EDIM, EDIM, EDIM);

    // fused attention over hs
    attn_kernel<<<BATCH, 256>>>(hs, qk, hbar);

    // attn_out = hbar @ Amat^T + aconst; merged[:, :DM] = [attn_out, s]
    gemm_med<false, false><<<dim3(5, 8), 256>>>(hbar, Amat, aconst, ao, BATCH, EDIM, HID, HID, HID, EDIM);
    ms_build<<<(BATCH * DM + 255) / 256, 256>>>(ao, s, merged);

    // VQC (writes qfeat into merged[:, DM:])
    vqc_kernel<<<BATCH, 512>>>(merged, qweights);

    // MLP (reads merged directly, lda = NMERG)
    gemm_med<false, true><<<dim3(8, 8), 256>>>(merged, W1, b1, x1, BATCH, NL1, NMERG, NMERG, NMERG, NL1);
    gemm_med<false, false><<<dim3(1, 8), 256>>>(x1, W2, b2, out, BATCH, NACT, NL1, NL1, NL1, NACT);
}

// round 12
// speedup vs baseline: 1.8124x; 1.2512x over previous
#include <cuda_runtime.h>
#include <cuda_fp16.h>
#include <math.h>
#include <stdint.h>

#define BATCH 512
#define TSEQ  256
#define DIN   128
#define HID   256
#define G4    1024
#define FDIM  64
#define EDIM  320
#define DM    384
#define NMERG 394
#define NL1   512
#define NACT  8

#define NBLK   128   // lstm blocks: 16 batch-groups x 8 col-tiles
#define NGRP   8     // blocks per batch-group barrier
#define NPRE   20    // precompose blocks riding along in lstm_persist

// ---------------- scratch (static device memory; no allocations) ----------------
__device__ __half d_hs[33554432];      // [B, T, H] fp16 hidden states
__device__ __half d_hbuf[2 * BATCH * HID]; // double-buffered compact h (fp16)
__device__ int   d_bar[16 * TSEQ + 1]; // per (group, step) barriers + [last] = precompose bar
__device__ float d_Wip[G4 * DIN];      // permuted W_ih
__device__ float d_Wp[G4 * HID];       // permuted W_hh
__device__ float d_bp[G4];             // permuted bias
__device__ float d_sf[BATCH * EDIM];   // state_full
__device__ float d_qk[BATCH * HID];
__device__ float d_Mkp[EDIM * HID];    // Wk @ proj_W
__device__ float d_MA1[EDIM * HID];    // Wv @ proj_W
__device__ float d_Amat[EDIM * HID];   // Wo @ Wv @ proj_W
__device__ float d_P[EDIM * HID];      // Wq^T @ Mkp
__device__ float d_cqk[HID];           // bq @ Mkp
__device__ float d_aconst[EDIM];
__device__ float d_hbar[BATCH * HID];
__device__ float d_ao[BATCH * EDIM];
__device__ float d_merged[BATCH * NMERG];  // [merged_state | qfeat]
__device__ float d_x1[BATCH * NL1];

// ---------------- fp16 mma helpers ----------------
__device__ __forceinline__ uint32_t pack_h2(float x, float y) {
    __half2 t = __floats2half2_rn(x, y);
    return *reinterpret_cast<uint32_t*>(&t);
}
__device__ __forceinline__ void mma_f16(float* c, uint32_t a0, uint32_t a1,
                                        uint32_t a2, uint32_t a3,
                                        uint32_t b0, uint32_t b1) {
    asm volatile("mma.sync.aligned.m16n8k16.row.col.f32.f16.f16.f32 "
        "{%0,%1,%2,%3}, {%4,%5,%6,%7}, {%8,%9}, {%0,%1,%2,%3};"
        : "+f"(c[0]), "+f"(c[1]), "+f"(c[2]), "+f"(c[3])
        : "r"(a0), "r"(a1), "r"(a2), "r"(a3), "r"(b0), "r"(b1));
}
__device__ __forceinline__ float fsig(float x) {
    return __fdividef(1.f, 1.f + __expf(-x));
}
__device__ __forceinline__ float ftanh(float x) {
    return 2.f * fsig(2.f * x) - 1.f;
}

// ---------------- weight permutation: column 4u+g = gate g of unit u ----------------
__global__ void permute_kernel(const float* __restrict__ W_ih, const float* __restrict__ W_hh,
                               const float* __restrict__ b_ih, const float* __restrict__ b_hh,
                               float* __restrict__ Wip, float* __restrict__ Wp, float* __restrict__ bp) {
    int n = blockIdx.x;            // 0..1023, permuted row
    int u = n >> 2, g = n & 3;
    int o = g * HID + u;           // original row
    for (int k = threadIdx.x; k < DIN; k += blockDim.x) Wip[n * DIN + k] = W_ih[o * DIN + k];
    for (int k = threadIdx.x; k < HID; k += blockDim.x) Wp[n * HID + k] = W_hh[o * HID + k];
    if (threadIdx.x == 0) bp[n] = b_ih[o] + b_hh[o];
}

// ---------------- 64x64 fp32 tile GEMM (device; used by precompose blocks) -----------
// C[r,n] = sum_k opA(A)[r,k] * B[k*ldb + n],  r,n in [0,64), pointers pre-offset.
__device__ void tile64(const float* __restrict__ A, int lda, bool transA,
                       const float* __restrict__ B, int ldb,
                       float* __restrict__ C, int ldc, int K, int tid,
                       float (*sA)[68], float (*sW)[68]) {
    int tx = tid & 15, ty = tid >> 4;
    float acc[4][4] = {};
    for (int k0 = 0; k0 < K; k0 += 16) {
        #pragma unroll
        for (int i = 0; i < 4; i++) {
            int idx = tid + i * 256;
            int r = idx >> 4, k = idx & 15;
            sA[k][r] = transA ? A[(size_t)(k0 + k) * lda + r]
                              : A[(size_t)r * lda + k0 + k];
            sW[k][r] = B[(size_t)(k0 + k) * ldb + r];
        }
        __syncthreads();
        #pragma unroll
        for (int k = 0; k < 16; k++) {
            float4 a = *(const float4*)&sA[k][ty * 4];
            float4 b = *(const float4*)&sW[k][tx * 4];
            acc[0][0] += a.x * b.x; acc[0][1] += a.x * b.y; acc[0][2] += a.x * b.z; acc[0][3] += a.x * b.w;
            acc[1][0] += a.y * b.x; acc[1][1] += a.y * b.y; acc[1][2] += a.y * b.z; acc[1][3] += a.y * b.w;
            acc[2][0] += a.z * b.x; acc[2][1] += a.z * b.y; acc[2][2] += a.z * b.z; acc[2][3] += a.z * b.w;
            acc[3][0] += a.w * b.x; acc[3][1] += a.w * b.y; acc[3][2] += a.w * b.z; acc[3][3] += a.w * b.w;
        }
        __syncthreads();
    }
    #pragma unroll
    for (int r = 0; r < 4; r++)
        #pragma unroll
        for (int cc = 0; cc < 4; cc++)
            C[(size_t)(ty * 4 + r) * ldc + tx * 4 + cc] = acc[r][cc];
}

// ---------------- persistent fused LSTM + hidden weight precompose -------------------
// Blocks [0,128): LSTM recurrence (fused input GEMM, fp16 mma, xw-free).
// Blocks [128,148): attention weight precompose, hidden under the recurrence.
__global__ __launch_bounds__(256, 1) void lstm_persist(
    const float* __restrict__ X, const float* __restrict__ Wip,
    const float* __restrict__ Wp, const float* __restrict__ bp,
    __half* __restrict__ hs, __half* __restrict__ hbuf, int* __restrict__ bar,
    const float* __restrict__ in_proj_W, const float* __restrict__ in_proj_b,
    const float* __restrict__ proj_W, const float* __restrict__ proj_b,
    const float* __restrict__ out_proj_W, const float* __restrict__ out_proj_b,
    float* __restrict__ Mkp, float* __restrict__ MA1, float* __restrict__ Amat,
    float* __restrict__ P, float* __restrict__ cqk, float* __restrict__ aconst)
{
    __shared__ __half sA[32][264];   // h tile
    __shared__ __half sX[32][136];   // x tile
    __shared__ float tA[16][68];     // precompose tiles
    __shared__ float tB[16][68];
    __shared__ float svc[EDIM];
    int tid = threadIdx.x;

    // ===================== precompose blocks =====================
    if (blockIdx.x >= NBLK) {
        int p = blockIdx.x - NBLK;   // 0..19
        volatile int* pbar = bar + 16 * TSEQ;
        const float* Wq   = in_proj_W;
        const float* WkWv = in_proj_W + EDIM * EDIM;   // [Wk; Wv], 640 x 320
        // phase A: [Wk;Wv] @ proj_W  → Mkp rows [0,320), MA1 rows [0,320)
        for (int tix = p; tix < 40; tix += NPRE) {
            int tm = tix >> 2, tn = tix & 3;
            int mg = tm * 64;
            float* Crow = (mg < EDIM) ? (Mkp + (size_t)mg * HID)
                                      : (MA1 + (size_t)(mg - EDIM) * HID);
            tile64(WkWv + (size_t)mg * EDIM, EDIM, false,
                   proj_W + tn * 64, HID,
                   Crow + tn * 64, HID, EDIM, tid, tA, tB);
        }
        __threadfence();
        __syncthreads();
        if (tid == 0) {
            atomicAdd((int*)(bar + 16 * TSEQ), 1);
            while (pbar[0] < NPRE) {}
        }
        __syncthreads();
        // phase B: Amat = Wo @ MA1 ; P = Wq^T @ Mkp   (20 tiles each, 1 per block)
        {
            int tm = p >> 2, tn = p & 3;
            tile64(out_proj_W + (size_t)tm * 64 * EDIM, EDIM, false,
                   MA1 + tn * 64, HID,
                   Amat + (size_t)tm * 64 * HID + tn * 64, HID, EDIM, tid, tA, tB);
            tile64(Wq + tm * 64, EDIM, true,
                   Mkp + tn * 64, HID,
                   P + (size_t)tm * 64 * HID + tn * 64, HID, EDIM, tid, tA, tB);
        }
        if (p == 0) {
            // cqk[h] = sum_e bq[e] * Mkp[e,h]
            if (tid < HID) {
                float a = 0.f;
                for (int e = 0; e < EDIM; e++) a += in_proj_b[e] * Mkp[(size_t)e * HID + tid];
                cqk[tid] = a;
            }
        }
        if (p == 1) {
            // vconst (smem only) then aconst
            for (int e = tid; e < EDIM; e += 256) {
                float a = in_proj_b[2 * EDIM + e];
                const float* wr = in_proj_W + (size_t)(2 * EDIM + e) * EDIM;
                for (int k = 0; k < EDIM; k++) a += wr[k] * proj_b[k];
                svc[e] = a;
            }
            __syncthreads();
            for (int e = tid; e < EDIM; e += 256) {
                float a = out_proj_b[e];
                const float* wr = out_proj_W + (size_t)e * EDIM;
                for (int k = 0; k < EDIM; k++) a += wr[k] * svc[k];
                aconst[e] = a;
            }
        }
        return;
    }

    // ===================== LSTM blocks =====================
    int bx = blockIdx.x & 7;        // col tile (128 cols)
    int gid = blockIdx.x >> 3;      // batch group (0..15, 32 rows)
    int n0 = bx * 128, m0 = gid * 32;
    int wid = tid >> 5, lane = tid & 31;
    int g = lane >> 2, t4 = lane & 3;
    int warp_n = wid * 16;
    int odd = lane & 1;

    uint32_t bregh[2][16][2];
    uint32_t bregx[2][8][2];
    #pragma unroll
    for (int j = 0; j < 2; j++) {
        int col = n0 + warp_n + 8 * j + g;
        const float* wrow = Wp + (size_t)col * HID;
        #pragma unroll
        for (int kk = 0; kk < 16; kk++) {
            bregh[j][kk][0] = pack_h2(__ldg(wrow + kk * 16 + 2 * t4),
                                      __ldg(wrow + kk * 16 + 2 * t4 + 1));
            bregh[j][kk][1] = pack_h2(__ldg(wrow + kk * 16 + 2 * t4 + 8),
                                      __ldg(wrow + kk * 16 + 2 * t4 + 9));
        }
        const float* xrow = Wip + (size_t)col * DIN;
        #pragma unroll
        for (int kk = 0; kk < 8; kk++) {
            bregx[j][kk][0] = pack_h2(__ldg(xrow + kk * 16 + 2 * t4),
                                      __ldg(xrow + kk * 16 + 2 * t4 + 1));
            bregx[j][kk][1] = pack_h2(__ldg(xrow + kk * 16 + 2 * t4 + 8),
                                      __ldg(xrow + kk * 16 + 2 * t4 + 9));
        }
    }
    float creg[4] = {0.f, 0.f, 0.f, 0.f};
    volatile int* vbar = bar;

    int erow[2], eu;
    erow[0] = m0 + g + (odd ? 8 : 0);
    erow[1] = erow[0] + 16;
    eu = ((n0 + warp_n) >> 2) + ((lane >> 1) & 1);
    float4 bb[2];
    #pragma unroll
    for (int j = 0; j < 2; j++) bb[j] = *(const float4*)(bp + 4 * (eu + 2 * j));

    // preload x tile for t=0
    #pragma unroll
    for (int itr = 0; itr < 4; itr++) {
        int gi = itr * 256 + tid;
        int row = gi >> 5;
        int c4 = gi & 31;
        float4 v = __ldg((const float4*)(X + ((size_t)(m0 + row) * TSEQ + 0) * DIN + c4 * 4));
        uint2 pk = { pack_h2(v.x, v.y), pack_h2(v.z, v.w) };
        *(uint2*)&sX[row][c4 * 4] = pk;
    }
    __syncthreads();

    for (int t = 0; t < TSEQ; t++) {
        float c[2][2][4];
        #pragma unroll
        for (int i = 0; i < 2; i++)
            #pragma unroll
            for (int j = 0; j < 2; j++)
                #pragma unroll
                for (int e = 0; e < 4; e++) c[i][j][e] = 0.f;

        if (t > 0) {
            const __half* hp = hbuf + (size_t)(t & 1) * (BATCH * HID);
            #pragma unroll
            for (int itr = 0; itr < 4; itr++) {
                int gi = itr * 256 + tid;
                int row = gi >> 5;
                int s2 = gi & 31;
                uint4 v = __ldcg((const uint4*)(hp + (size_t)(m0 + row) * HID + s2 * 8));
                *(uint4*)&sA[row][s2 * 8] = v;
            }
            __syncthreads();
            #pragma unroll
            for (int kk = 0; kk < 16; kk++) {
                #pragma unroll
                for (int i = 0; i < 2; i++) {
                    int r0 = 16 * i + g;
                    const __half* alo = &sA[r0][kk * 16 + 2 * t4];
                    const __half* ahi = &sA[r0 + 8][kk * 16 + 2 * t4];
                    uint32_t a0 = *(const uint32_t*)alo;
                    uint32_t a2 = *(const uint32_t*)(alo + 8);
                    uint32_t a1 = *(const uint32_t*)ahi;
                    uint32_t a3 = *(const uint32_t*)(ahi + 8);
                    mma_f16(c[i][0], a0, a1, a2, a3, bregh[0][kk][0], bregh[0][kk][1]);
                    mma_f16(c[i][1], a0, a1, a2, a3, bregh[1][kk][0], bregh[1][kk][1]);
                }
            }
        }
        #pragma unroll
        for (int kk = 0; kk < 8; kk++) {
            #pragma unroll
            for (int i = 0; i < 2; i++) {
                int r0 = 16 * i + g;
                const __half* alo = &sX[r0][kk * 16 + 2 * t4];
                const __half* ahi = &sX[r0 + 8][kk * 16 + 2 * t4];
                uint32_t a0 = *(const uint32_t*)alo;
                uint32_t a2 = *(const uint32_t*)(alo + 8);
                uint32_t a1 = *(const uint32_t*)ahi;
                uint32_t a3 = *(const uint32_t*)(ahi + 8);
                mma_f16(c[i][0], a0, a1, a2, a3, bregx[0][kk][0], bregx[0][kk][1]);
                mma_f16(c[i][1], a0, a1, a2, a3, bregx[1][kk][0], bregx[1][kk][1]);
            }
        }

        __half* hn = hbuf + (size_t)((t + 1) & 1) * (BATCH * HID);
        float hvreg[2][2];
        #pragma unroll
        for (int i = 0; i < 2; i++) {
            #pragma unroll
            for (int j = 0; j < 2; j++) {
                float u0 = odd ? c[i][j][0] : c[i][j][2];
                float u1 = odd ? c[i][j][1] : c[i][j][3];
                float rx0 = __shfl_xor_sync(0xffffffffu, u0, 1);
                float rx1 = __shfl_xor_sync(0xffffffffu, u1, 1);
                float gi, gf, gg, go;
                if (!odd) { gi = c[i][j][0]; gf = c[i][j][1]; gg = rx0; go = rx1; }
                else      { gi = rx0; gf = rx1; gg = c[i][j][2]; go = c[i][j][3]; }
                gi += bb[j].x; gf += bb[j].y; gg += bb[j].z; go += bb[j].w;
                int brow = erow[i];
                int u = eu + 2 * j;
                float i_ = fsig(gi);
                float f_ = fsig(gf);
                float g_ = ftanh(gg);
                float o_ = fsig(go);
                int ci = i * 2 + j;
                float cn = f_ * creg[ci] + i_ * g_;
                creg[ci] = cn;
                float hv = o_ * ftanh(cn);
                hvreg[i][j] = hv;
                hn[(size_t)brow * HID + u] = __float2half_rn(hv);
            }
        }

        int bi = gid * TSEQ + t;
        if (t < TSEQ - 1) {
            __threadfence();
            __syncthreads();
            if (tid == 0) atomicAdd(&bar[bi], 1);
            #pragma unroll
            for (int itr = 0; itr < 4; itr++) {
                int gi = itr * 256 + tid;
                int row = gi >> 5;
                int c4 = gi & 31;
                float4 v = __ldg((const float4*)(X + ((size_t)(m0 + row) * TSEQ + (t + 1)) * DIN + c4 * 4));
                uint2 pk = { pack_h2(v.x, v.y), pack_h2(v.z, v.w) };
                *(uint2*)&sX[row][c4 * 4] = pk;
            }
        }
        #pragma unroll
        for (int i = 0; i < 2; i++)
            #pragma unroll
            for (int j = 0; j < 2; j++)
                hs[((size_t)erow[i] * TSEQ + t) * HID + eu + 2 * j] = __float2half_rn(hvreg[i][j]);
        if (t < TSEQ - 1) {
            if (tid == 0) { while (vbar[bi] < NGRP) {} }
            __syncthreads();
        }
    }
}

// ---------------- medium GEMM with register double-buffering --------------------------
template <bool TRANS, bool RELU>
__global__ __launch_bounds__(256) void gemm_med(
    const float* __restrict__ A, const float* __restrict__ W,
    const float* __restrict__ bias, float* __restrict__ C,
    int M, int N, int K, int lda, int ldw, int ldc) {
    __shared__ float sA[16][68];   // [k][m]
    __shared__ float sW[16][68];   // [k][n]
    int m0 = blockIdx.y * 64, n0 = blockIdx.x * 64;
    int tid = threadIdx.x;
    int tx = tid & 15, ty = tid >> 4;
    float acc[4][4] = {};
    float pa[4], pw[4];

    #pragma unroll
    for (int i = 0; i < 4; i++) {
        int idx = tid + i * 256;
        int r = idx >> 4, k = idx & 15;
        int mm = m0 + r, kk = k;
        pa[i] = (mm < M && kk < K) ? A[(size_t)mm * lda + kk] : 0.f;
        int nn = n0 + r;
        float v = 0.f;
        if (TRANS) { if (kk < K && nn < N) v = W[(size_t)kk * ldw + nn]; }
        else       { if (nn < N && kk < K) v = W[(size_t)nn * ldw + kk]; }
        pw[i] = v;
    }
    for (int k0 = 0; k0 < K; k0 += 16) {
        #pragma unroll
        for (int i = 0; i < 4; i++) {
            int idx = tid + i * 256;
            int r = idx >> 4, k = idx & 15;
            sA[k][r] = pa[i];
            sW[k][r] = pw[i];
        }
        __syncthreads();
        if (k0 + 16 < K) {
            #pragma unroll
            for (int i = 0; i < 4; i++) {
                int idx = tid + i * 256;
                int r = idx >> 4, k = idx & 15;
                int mm = m0 + r, kk = k0 + 16 + k;
                pa[i] = (mm < M && kk < K) ? A[(size_t)mm * lda + kk] : 0.f;
                int nn = n0 + r;
                float v = 0.f;
                if (TRANS) { if (kk < K && nn < N) v = W[(size_t)kk * ldw + nn]; }
                else       { if (nn < N && kk < K) v = W[(size_t)nn * ldw + kk]; }
                pw[i] = v;
            }
        }
        #pragma unroll
        for (int k = 0; k < 16; k++) {
            float4 a = *(const float4*)&sA[k][ty * 4];
            float4 b = *(const float4*)&sW[k][tx * 4];
            acc[0][0] += a.x * b.x; acc[0][1] += a.x * b.y; acc[0][2] += a.x * b.z; acc[0][3] += a.x * b.w;
            acc[1][0] += a.y * b.x; acc[1][1] += a.y * b.y; acc[1][2] += a.y * b.z; acc[1][3] += a.y * b.w;
            acc[2][0] += a.z * b.x; acc[2][1] += a.z * b.y; acc[2][2] += a.z * b.z; acc[2][3] += a.z * b.w;
            acc[3][0] += a.w * b.x; acc[3][1] += a.w * b.y; acc[3][2] += a.w * b.z; acc[3][3] += a.w * b.w;
        }
        __syncthreads();
    }
    #pragma unroll
    for (int r = 0; r < 4; r++) {
        int m = m0 + ty * 4 + r;
        if (m >= M) continue;
        #pragma unroll
        for (int cc = 0; cc < 4; cc++) {
            int n = n0 + tx * 4 + cc;
            if (n >= N) continue;
            float v = acc[r][cc];
            if (bias) v += bias[n];
            if (RELU) v = fmaxf(v, 0.f);
            C[(size_t)m * ldc + n] = v;
        }
    }
}

// ---------------- fused attention over fp16 hs ---------------------------------------
__global__ void attn_kernel(const __half* __restrict__ hs, const float* __restrict__ qk,
                            float* __restrict__ hbar) {
    int b = blockIdx.x;
    __shared__ float sc[TSEQ];
    __shared__ float red[256];
    __shared__ float sqk[HID];
    int tid = threadIdx.x;
    int lane = tid & 31, w = tid >> 5;
    sqk[tid] = qk[b * HID + tid];
    __syncthreads();
    for (int t = w; t < TSEQ; t += 8) {
        const __half2* hrow = (const __half2*)(hs + ((size_t)b * TSEQ + t) * HID);
        float p = 0.f;
        #pragma unroll
        for (int j = 0; j < 4; j++) {
            int h2i = lane + 32 * j;
            float2 hv = __half22float2(hrow[h2i]);
            p += hv.x * sqk[2 * h2i] + hv.y * sqk[2 * h2i + 1];
        }
        #pragma unroll
        for (int o = 16; o > 0; o >>= 1) p += __shfl_down_sync(0xffffffffu, p, o);
        if (lane == 0) sc[t] = p;
    }
    __syncthreads();
    float scale = 1.0f / sqrtf((float)EDIM);
    float v = sc[tid] * scale;
    red[tid] = v; __syncthreads();
    for (int s = 128; s > 0; s >>= 1) { if (tid < s) red[tid] = fmaxf(red[tid], red[tid + s]); __syncthreads(); }
    float mx = red[0]; __syncthreads();
    float ev = expf(v - mx);
    red[tid] = ev; __syncthreads();
    for (int s = 128; s > 0; s >>= 1) { if (tid < s) red[tid] += red[tid + s]; __syncthreads(); }
    float sum = red[0]; __syncthreads();
    sc[tid] = ev / sum;
    __syncthreads();
    const __half* hb = hs + (size_t)b * TSEQ * HID;
    float acc = 0.f;
    for (int t = 0; t < TSEQ; t++) acc += sc[t] * __half2float(hb[(size_t)t * HID + tid]);
    hbar[b * HID + tid] = acc;
}

// ---------------- concat helpers ----------------
__global__ void sf_build(const __half* __restrict__ hs, const float* __restrict__ s,
                         float* __restrict__ sf) {
    int idx = blockIdx.x * blockDim.x + threadIdx.x;
    if (idx >= BATCH * EDIM) return;
    int b = idx / EDIM, j = idx % EDIM;
    sf[idx] = (j < HID) ? __half2float(hs[((size_t)b * TSEQ + (TSEQ - 1)) * HID + j])
                        : s[b * FDIM + (j - HID)];
}
__global__ void ms_build(const float* __restrict__ ao, const float* __restrict__ s,
                         float* __restrict__ merged) {
    int idx = blockIdx.x * blockDim.x + threadIdx.x;
    if (idx >= BATCH * DM) return;
    int b = idx / DM, j = idx % DM;
    merged[(size_t)b * NMERG + j] = (j < EDIM) ? ao[b * EDIM + j] : s[b * FDIM + (j - EDIM)];
}

// ---------------- 10-qubit VQC; reads merged[:, :40], writes merged[:, DM:DM+10] -----
struct c2f { float x, y; };
__device__ __forceinline__ c2f cmul(c2f a, c2f b) { return { a.x * b.x - a.y * b.y, a.x * b.y + a.y * b.x }; }
__device__ __forceinline__ c2f cadd(c2f a, c2f b) { return { a.x + b.x, a.y + b.y }; }
__device__ __forceinline__ void matmul2(c2f C[2][2], const c2f A[2][2], const c2f B[2][2]) {
    #pragma unroll
    for (int i = 0; i < 2; i++)
        #pragma unroll
        for (int j = 0; j < 2; j++)
            C[i][j] = cadd(cmul(A[i][0], B[0][j]), cmul(A[i][1], B[1][j]));
}

__global__ void vqc_kernel(float* __restrict__ merged, const float* __restrict__ qw) {
    int b = blockIdx.x;
    __shared__ c2f psi[1024];
    __shared__ float red[512];
    __shared__ float sang[40];
    int tid = threadIdx.x;
    const float PI_F = 3.14159265358979323846f;
    psi[tid] = { 0.03125f, 0.f };
    psi[tid + 512] = { 0.03125f, 0.f };
    if (tid < 40) sang[tid] = tanhf(merged[(size_t)b * NMERG + tid]) * PI_F;
    __syncthreads();

    for (int layer = 0; layer < 4; layer++) {
        for (int q = 0; q < 10; q++) {
            int idx = layer * 10 + q;
            float a = sang[idx];
            float w0 = qw[idx * 3 + 0], w1 = qw[idx * 3 + 1], w2 = qw[idx * 3 + 2];
            float ch, sh; sincosf(0.5f * a, &sh, &ch);
            c2f Rx[2][2] = { { {ch, 0.f}, {0.f, -sh} }, { {0.f, -sh}, {ch, 0.f} } };
            c2f Rya[2][2] = { { {ch, 0.f}, {-sh, 0.f} }, { {sh, 0.f}, {ch, 0.f} } };
            c2f T1[2][2]; matmul2(T1, Rya, Rx);
            float c0, s0; sincosf(0.5f * w0, &s0, &c0);
            c2f Rz0[2][2] = { { {c0, -s0}, {0.f, 0.f} }, { {0.f, 0.f}, {c0, s0} } };
            c2f T2[2][2]; matmul2(T2, Rz0, T1);
            float c1, s1; sincosf(0.5f * w1, &s1, &c1);
            c2f Ry1[2][2] = { { {c1, 0.f}, {-s1, 0.f} }, { {s1, 0.f}, {c1, 0.f} } };
            c2f T3[2][2]; matmul2(T3, Ry1, T2);
            float c2r, s2r; sincosf(0.5f * w2, &s2r, &c2r);
            c2f Rz2[2][2] = { { {c2r, -s2r}, {0.f, 0.f} }, { {0.f, 0.f}, {c2r, s2r} } };
            c2f U[2][2]; matmul2(U, Rz2, T3);

            int bq = 9 - q;
            int low = tid & ((1 << bq) - 1);
            int i0 = ((tid >> bq) << (bq + 1)) | low;
            int i1 = i0 | (1 << bq);
            __syncthreads();
            c2f a0 = psi[i0], a1 = psi[i1];
            psi[i0] = cadd(cmul(U[0][0], a0), cmul(U[0][1], a1));
            psi[i1] = cadd(cmul(U[1][0], a0), cmul(U[1][1], a1));
        }
        for (int qq = 0; qq < 10; qq++) {
            int ctrl = (qq < 9) ? qq : 9;
            int tgt  = (qq < 9) ? qq + 1 : 0;
            int bc = 9 - ctrl, bt = 9 - tgt;
            __syncthreads();
            if (tid < 256) {
                int lo = min(bc, bt), hi = max(bc, bt);
                int i = tid;
                i = ((i >> lo) << (lo + 1)) | (i & ((1 << lo) - 1));
                i = ((i >> hi) << (hi + 1)) | (i & ((1 << hi) - 1));
                i |= (1 << bc);
                int j0 = i;
                int j1 = i | (1 << bt);
                c2f tmp = psi[j0]; psi[j0] = psi[j1]; psi[j1] = tmp;
            }
        }
    }
    __syncthreads();
    c2f p0 = psi[tid], p1 = psi[tid + 512];
    float n0 = p0.x * p0.x + p0.y * p0.y;
    float n1 = p1.x * p1.x + p1.y * p1.y;
    for (int k = 0; k < 10; k++) {
        int bp_ = 9 - k;
        float s0v = ((tid >> bp_) & 1) ? -n0 : n0;
        float s1v = (((tid + 512) >> bp_) & 1) ? -n1 : n1;
        red[tid] = s0v + s1v;
        __syncthreads();
        for (int s = 256; s > 0; s >>= 1) { if (tid < s) red[tid] += red[tid + s]; __syncthreads(); }
        if (tid == 0) merged[(size_t)b * NMERG + DM + k] = red[0];
        __syncthreads();
    }
}

// ---------------- host launch ----------------
#define GETSYM(p, sym) do { void* _t = nullptr; cudaGetSymbolAddress(&_t, sym); (p) = (float*)_t; } while (0)

extern "C" void kernel_launch(void* const* d_in, const int* in_sizes, int n_in,
                              void* d_out, int out_size) {
    const float* s          = (const float*)d_in[0];
    const float* lstm_s     = (const float*)d_in[1];
    const float* W_ih       = (const float*)d_in[2];
    const float* W_hh       = (const float*)d_in[3];
    const float* b_ih       = (const float*)d_in[4];
    const float* b_hh       = (const float*)d_in[5];
    const float* proj_W     = (const float*)d_in[6];
    const float* proj_b     = (const float*)d_in[7];
    const float* in_proj_W  = (const float*)d_in[8];
    const float* in_proj_b  = (const float*)d_in[9];
    const float* out_proj_W = (const float*)d_in[10];
    const float* out_proj_b = (const float*)d_in[11];
    const float* qweights   = (const float*)d_in[12];
    const float* W1         = (const float*)d_in[13];
    const float* b1         = (const float*)d_in[14];
    const float* W2         = (const float*)d_in[15];
    const float* b2         = (const float*)d_in[16];
    float* out = (float*)d_out;

    float *Wip, *Wp, *bp, *sf, *qk, *Mkp, *MA1, *Amat, *P, *cqk;
    float *aconst, *hbar, *ao, *merged, *x1;
    __half *hbuf, *hs;
    int* bar;
    { void* _t = nullptr; cudaGetSymbolAddress(&_t, d_hbuf); hbuf = (__half*)_t; }
    { void* _t = nullptr; cudaGetSymbolAddress(&_t, d_hs); hs = (__half*)_t; }
    GETSYM(Wip, d_Wip); GETSYM(Wp, d_Wp);   GETSYM(bp, d_bp);   GETSYM(sf, d_sf);
    GETSYM(qk, d_qk);   GETSYM(Mkp, d_Mkp); GETSYM(MA1, d_MA1);
    GETSYM(Amat, d_Amat); GETSYM(P, d_P);   GETSYM(cqk, d_cqk);
    GETSYM(aconst, d_aconst);
    GETSYM(hbar, d_hbar); GETSYM(ao, d_ao);
    GETSYM(merged, d_merged); GETSYM(x1, d_x1);
    { void* _t = nullptr; cudaGetSymbolAddress(&_t, d_bar); bar = (int*)_t; }

    cudaMemsetAsync(bar, 0, (16 * TSEQ + 1) * sizeof(int));

    // weight permutation (gate-interleaved)
    permute_kernel<<<G4, 128>>>(W_ih, W_hh, b_ih, b_hh, Wip, Wp, bp);

    // persistent fused LSTM + hidden attention-weight precompose
    lstm_persist<<<NBLK + NPRE, 256>>>(lstm_s, Wip, Wp, bp, hs, hbuf, bar,
                                       in_proj_W, in_proj_b, proj_W, proj_b,
                                       out_proj_W, out_proj_b,
                                       Mkp, MA1, Amat, P, cqk, aconst);

    // state_full = [h_last, s]; qk = sf @ P + cqk  (q-GEMM folded into P)
    sf_build<<<(BATCH * EDIM + 255) / 256, 256>>>(hs, s, sf);
    gemm_med<true, false><<<dim3(4, 8), 256>>>(sf, P, cqk, qk, BATCH, HID, EDIM, EDIM, HID, HID);

    // fused attention over hs
    attn_kernel<<<BATCH, 256>>>(hs, qk, hbar);

    // attn_out = hbar @ Amat^T + aconst; merged[:, :DM] = [attn_out, s]
    gemm_med<false, false><<<dim3(5, 8), 256>>>(hbar, Amat, aconst, ao, BATCH, EDIM, HID, HID, HID, EDIM);
    ms_build<<<(BATCH * DM + 255) / 256, 256>>>(ao, s, merged);

    // VQC (writes qfeat into merged[:, DM:])
    vqc_kernel<<<BATCH, 512>>>(merged, qweights);

    // MLP (reads merged directly, lda = NMERG)
    gemm_med<false, true><<<dim3(8, 8), 256>>>(merged, W1, b1, x1, BATCH, NL1, NMERG, NMERG, NMERG, NL1);
    gemm_med<false, false><<<dim3(1, 8), 256>>>(x1, W2, b2, out, BATCH, NACT, NL1, NL1, NL1, NACT);
}

// round 13
// speedup vs baseline: 1.8918x; 1.0438x over previous
#include <cuda_runtime.h>
#include <cuda_fp16.h>
#include <math.h>
#include <stdint.h>

#define BATCH 512
#define TSEQ  256
#define DIN   128
#define HID   256
#define G4    1024
#define FDIM  64
#define EDIM  320
#define DM    384
#define NMERG 394
#define NL1   512
#define NACT  8

#define NBLK   128   // lstm blocks: 16 batch-groups x 8 col-tiles
#define NGRP   8     // blocks per batch-group barrier
#define NPRE   20    // precompose blocks riding along in lstm_persist

// ---------------- scratch (static device memory; no allocations) ----------------
__device__ __half d_hs[33554432];      // [B, T, H] fp16 hidden states
__device__ __half d_hbuf[2 * BATCH * HID]; // double-buffered compact h (fp16)
__device__ int   d_bar[16 * TSEQ + 1]; // per (group, step) barriers + [last] = precompose bar
__device__ float d_sf[BATCH * EDIM];   // state_full
__device__ float d_qk[BATCH * HID];
__device__ float d_Mkp[EDIM * HID];    // Wk @ proj_W
__device__ float d_MA1[EDIM * HID];    // Wv @ proj_W
__device__ float d_Amat[EDIM * HID];   // Wo @ Wv @ proj_W
__device__ float d_P[EDIM * HID];      // Wq^T @ Mkp
__device__ float d_cqk[HID];           // bq @ Mkp
__device__ float d_aconst[EDIM];
__device__ float d_hbar[BATCH * HID];
__device__ float d_merged[BATCH * NMERG];  // [attn_out | s | qfeat]
__device__ float d_x1[BATCH * NL1];

// ---------------- fp16 mma helpers ----------------
__device__ __forceinline__ uint32_t pack_h2(float x, float y) {
    __half2 t = __floats2half2_rn(x, y);
    return *reinterpret_cast<uint32_t*>(&t);
}
__device__ __forceinline__ void mma_f16(float* c, uint32_t a0, uint32_t a1,
                                        uint32_t a2, uint32_t a3,
                                        uint32_t b0, uint32_t b1) {
    asm volatile("mma.sync.aligned.m16n8k16.row.col.f32.f16.f16.f32 "
        "{%0,%1,%2,%3}, {%4,%5,%6,%7}, {%8,%9}, {%0,%1,%2,%3};"
        : "+f"(c[0]), "+f"(c[1]), "+f"(c[2]), "+f"(c[3])
        : "r"(a0), "r"(a1), "r"(a2), "r"(a3), "r"(b0), "r"(b1));
}
__device__ __forceinline__ float fsig(float x) {
    return __fdividef(1.f, 1.f + __expf(-x));
}
__device__ __forceinline__ float ftanh(float x) {
    return 2.f * fsig(2.f * x) - 1.f;
}

// ---------------- 64x64 fp32 tile GEMM (device; used by precompose blocks) -----------
__device__ void tile64(const float* __restrict__ A, int lda, bool transA,
                       const float* __restrict__ B, int ldb,
                       float* __restrict__ C, int ldc, int K, int tid,
                       float (*sA)[68], float (*sW)[68]) {
    int tx = tid & 15, ty = tid >> 4;
    float acc[4][4] = {};
    for (int k0 = 0; k0 < K; k0 += 16) {
        #pragma unroll
        for (int i = 0; i < 4; i++) {
            int idx = tid + i * 256;
            int r = idx >> 4, k = idx & 15;
            sA[k][r] = transA ? A[(size_t)(k0 + k) * lda + r]
                              : A[(size_t)r * lda + k0 + k];
            sW[k][r] = B[(size_t)(k0 + k) * ldb + r];
        }
        __syncthreads();
        #pragma unroll
        for (int k = 0; k < 16; k++) {
            float4 a = *(const float4*)&sA[k][ty * 4];
            float4 b = *(const float4*)&sW[k][tx * 4];
            acc[0][0] += a.x * b.x; acc[0][1] += a.x * b.y; acc[0][2] += a.x * b.z; acc[0][3] += a.x * b.w;
            acc[1][0] += a.y * b.x; acc[1][1] += a.y * b.y; acc[1][2] += a.y * b.z; acc[1][3] += a.y * b.w;
            acc[2][0] += a.z * b.x; acc[2][1] += a.z * b.y; acc[2][2] += a.z * b.z; acc[2][3] += a.z * b.w;
            acc[3][0] += a.w * b.x; acc[3][1] += a.w * b.y; acc[3][2] += a.w * b.z; acc[3][3] += a.w * b.w;
        }
        __syncthreads();
    }
    #pragma unroll
    for (int r = 0; r < 4; r++)
        #pragma unroll
        for (int cc = 0; cc < 4; cc++)
            C[(size_t)(ty * 4 + r) * ldc + tx * 4 + cc] = acc[r][cc];
}

// ---------------- persistent fused LSTM + hidden weight precompose -------------------
// Blocks [0,128): LSTM recurrence (fused input GEMM, fp16 mma; weights gathered
// directly from W_ih/W_hh with the gate-interleave index map — no permute pass).
// Blocks [128,148): attention weight precompose, hidden under the recurrence.
__global__ __launch_bounds__(256, 1) void lstm_persist(
    const float* __restrict__ X, const float* __restrict__ W_ih,
    const float* __restrict__ W_hh, const float* __restrict__ b_ih,
    const float* __restrict__ b_hh,
    __half* __restrict__ hs, __half* __restrict__ hbuf, int* __restrict__ bar,
    const float* __restrict__ in_proj_W, const float* __restrict__ in_proj_b,
    const float* __restrict__ proj_W, const float* __restrict__ proj_b,
    const float* __restrict__ out_proj_W, const float* __restrict__ out_proj_b,
    float* __restrict__ Mkp, float* __restrict__ MA1, float* __restrict__ Amat,
    float* __restrict__ P, float* __restrict__ cqk, float* __restrict__ aconst)
{
    __shared__ __half sA[32][264];   // h tile
    __shared__ __half sX[32][136];   // x tile
    __shared__ float tA[16][68];     // precompose tiles
    __shared__ float tB[16][68];
    __shared__ float svc[EDIM];
    int tid = threadIdx.x;

    // ===================== precompose blocks =====================
    if (blockIdx.x >= NBLK) {
        int p = blockIdx.x - NBLK;   // 0..19
        volatile int* pbar = bar + 16 * TSEQ;
        const float* Wq   = in_proj_W;
        const float* WkWv = in_proj_W + EDIM * EDIM;   // [Wk; Wv], 640 x 320
        for (int tix = p; tix < 40; tix += NPRE) {
            int tm = tix >> 2, tn = tix & 3;
            int mg = tm * 64;
            float* Crow = (mg < EDIM) ? (Mkp + (size_t)mg * HID)
                                      : (MA1 + (size_t)(mg - EDIM) * HID);
            tile64(WkWv + (size_t)mg * EDIM, EDIM, false,
                   proj_W + tn * 64, HID,
                   Crow + tn * 64, HID, EDIM, tid, tA, tB);
        }
        __threadfence();
        __syncthreads();
        if (tid == 0) {
            atomicAdd((int*)(bar + 16 * TSEQ), 1);
            while (pbar[0] < NPRE) {}
        }
        __syncthreads();
        {
            int tm = p >> 2, tn = p & 3;
            tile64(out_proj_W + (size_t)tm * 64 * EDIM, EDIM, false,
                   MA1 + tn * 64, HID,
                   Amat + (size_t)tm * 64 * HID + tn * 64, HID, EDIM, tid, tA, tB);
            tile64(Wq + tm * 64, EDIM, true,
                   Mkp + tn * 64, HID,
                   P + (size_t)tm * 64 * HID + tn * 64, HID, EDIM, tid, tA, tB);
        }
        if (p == 0) {
            if (tid < HID) {
                float a = 0.f;
                for (int e = 0; e < EDIM; e++) a += in_proj_b[e] * Mkp[(size_t)e * HID + tid];
                cqk[tid] = a;
            }
        }
        if (p == 1) {
            for (int e = tid; e < EDIM; e += 256) {
                float a = in_proj_b[2 * EDIM + e];
                const float* wr = in_proj_W + (size_t)(2 * EDIM + e) * EDIM;
                for (int k = 0; k < EDIM; k++) a += wr[k] * proj_b[k];
                svc[e] = a;
            }
            __syncthreads();
            for (int e = tid; e < EDIM; e += 256) {
                float a = out_proj_b[e];
                const float* wr = out_proj_W + (size_t)e * EDIM;
                for (int k = 0; k < EDIM; k++) a += wr[k] * svc[k];
                aconst[e] = a;
            }
        }
        return;
    }

    // ===================== LSTM blocks =====================
    int bx = blockIdx.x & 7;        // col tile (128 cols)
    int gid = blockIdx.x >> 3;      // batch group (0..15, 32 rows)
    int n0 = bx * 128, m0 = gid * 32;
    int wid = tid >> 5, lane = tid & 31;
    int g = lane >> 2, t4 = lane & 3;
    int warp_n = wid * 16;
    int odd = lane & 1;

    uint32_t bregh[2][16][2];
    uint32_t bregx[2][8][2];
    #pragma unroll
    for (int j = 0; j < 2; j++) {
        int col = n0 + warp_n + 8 * j + g;          // permuted row (4u+gate)
        int o = (col & 3) * HID + (col >> 2);       // original row
        const float* wrow = W_hh + (size_t)o * HID;
        #pragma unroll
        for (int kk = 0; kk < 16; kk++) {
            bregh[j][kk][0] = pack_h2(__ldg(wrow + kk * 16 + 2 * t4),
                                      __ldg(wrow + kk * 16 + 2 * t4 + 1));
            bregh[j][kk][1] = pack_h2(__ldg(wrow + kk * 16 + 2 * t4 + 8),
                                      __ldg(wrow + kk * 16 + 2 * t4 + 9));
        }
        const float* xrow = W_ih + (size_t)o * DIN;
        #pragma unroll
        for (int kk = 0; kk < 8; kk++) {
            bregx[j][kk][0] = pack_h2(__ldg(xrow + kk * 16 + 2 * t4),
                                      __ldg(xrow + kk * 16 + 2 * t4 + 1));
            bregx[j][kk][1] = pack_h2(__ldg(xrow + kk * 16 + 2 * t4 + 8),
                                      __ldg(xrow + kk * 16 + 2 * t4 + 9));
        }
    }
    float creg[4] = {0.f, 0.f, 0.f, 0.f};
    volatile int* vbar = bar;

    int erow[2], eu;
    erow[0] = m0 + g + (odd ? 8 : 0);
    erow[1] = erow[0] + 16;
    eu = ((n0 + warp_n) >> 2) + ((lane >> 1) & 1);
    float4 bb[2];
    #pragma unroll
    for (int j = 0; j < 2; j++) {
        int u = eu + 2 * j;
        bb[j].x = __ldg(b_ih + u)           + __ldg(b_hh + u);
        bb[j].y = __ldg(b_ih + HID + u)     + __ldg(b_hh + HID + u);
        bb[j].z = __ldg(b_ih + 2 * HID + u) + __ldg(b_hh + 2 * HID + u);
        bb[j].w = __ldg(b_ih + 3 * HID + u) + __ldg(b_hh + 3 * HID + u);
    }

    // preload x tile for t=0
    #pragma unroll
    for (int itr = 0; itr < 4; itr++) {
        int gi = itr * 256 + tid;
        int row = gi >> 5;
        int c4 = gi & 31;
        float4 v = __ldg((const float4*)(X + ((size_t)(m0 + row) * TSEQ + 0) * DIN + c4 * 4));
        uint2 pk = { pack_h2(v.x, v.y), pack_h2(v.z, v.w) };
        *(uint2*)&sX[row][c4 * 4] = pk;
    }
    __syncthreads();

    for (int t = 0; t < TSEQ; t++) {
        float c[2][2][4];
        #pragma unroll
        for (int i = 0; i < 2; i++)
            #pragma unroll
            for (int j = 0; j < 2; j++)
                #pragma unroll
                for (int e = 0; e < 4; e++) c[i][j][e] = 0.f;

        if (t > 0) {
            const __half* hp = hbuf + (size_t)(t & 1) * (BATCH * HID);
            #pragma unroll
            for (int itr = 0; itr < 4; itr++) {
                int gi = itr * 256 + tid;
                int row = gi >> 5;
                int s2 = gi & 31;
                uint4 v = __ldcg((const uint4*)(hp + (size_t)(m0 + row) * HID + s2 * 8));
                *(uint4*)&sA[row][s2 * 8] = v;
            }
            __syncthreads();
            #pragma unroll
            for (int kk = 0; kk < 16; kk++) {
                #pragma unroll
                for (int i = 0; i < 2; i++) {
                    int r0 = 16 * i + g;
                    const __half* alo = &sA[r0][kk * 16 + 2 * t4];
                    const __half* ahi = &sA[r0 + 8][kk * 16 + 2 * t4];
                    uint32_t a0 = *(const uint32_t*)alo;
                    uint32_t a2 = *(const uint32_t*)(alo + 8);
                    uint32_t a1 = *(const uint32_t*)ahi;
                    uint32_t a3 = *(const uint32_t*)(ahi + 8);
                    mma_f16(c[i][0], a0, a1, a2, a3, bregh[0][kk][0], bregh[0][kk][1]);
                    mma_f16(c[i][1], a0, a1, a2, a3, bregh[1][kk][0], bregh[1][kk][1]);
                }
            }
        }
        #pragma unroll
        for (int kk = 0; kk < 8; kk++) {
            #pragma unroll
            for (int i = 0; i < 2; i++) {
                int r0 = 16 * i + g;
                const __half* alo = &sX[r0][kk * 16 + 2 * t4];
                const __half* ahi = &sX[r0 + 8][kk * 16 + 2 * t4];
                uint32_t a0 = *(const uint32_t*)alo;
                uint32_t a2 = *(const uint32_t*)(alo + 8);
                uint32_t a1 = *(const uint32_t*)ahi;
                uint32_t a3 = *(const uint32_t*)(ahi + 8);
                mma_f16(c[i][0], a0, a1, a2, a3, bregx[0][kk][0], bregx[0][kk][1]);
                mma_f16(c[i][1], a0, a1, a2, a3, bregx[1][kk][0], bregx[1][kk][1]);
            }
        }

        __half* hn = hbuf + (size_t)((t + 1) & 1) * (BATCH * HID);
        float hvreg[2][2];
        #pragma unroll
        for (int i = 0; i < 2; i++) {
            #pragma unroll
            for (int j = 0; j < 2; j++) {
                float u0 = odd ? c[i][j][0] : c[i][j][2];
                float u1 = odd ? c[i][j][1] : c[i][j][3];
                float rx0 = __shfl_xor_sync(0xffffffffu, u0, 1);
                float rx1 = __shfl_xor_sync(0xffffffffu, u1, 1);
                float gi, gf, gg, go;
                if (!odd) { gi = c[i][j][0]; gf = c[i][j][1]; gg = rx0; go = rx1; }
                else      { gi = rx0; gf = rx1; gg = c[i][j][2]; go = c[i][j][3]; }
                gi += bb[j].x; gf += bb[j].y; gg += bb[j].z; go += bb[j].w;
                int brow = erow[i];
                int u = eu + 2 * j;
                float i_ = fsig(gi);
                float f_ = fsig(gf);
                float g_ = ftanh(gg);
                float o_ = fsig(go);
                int ci = i * 2 + j;
                float cn = f_ * creg[ci] + i_ * g_;
                creg[ci] = cn;
                float hv = o_ * ftanh(cn);
                hvreg[i][j] = hv;
                hn[(size_t)brow * HID + u] = __float2half_rn(hv);
            }
        }

        int bi = gid * TSEQ + t;
        if (t < TSEQ - 1) {
            __threadfence();
            __syncthreads();
            if (tid == 0) atomicAdd(&bar[bi], 1);
            #pragma unroll
            for (int itr = 0; itr < 4; itr++) {
                int gi = itr * 256 + tid;
                int row = gi >> 5;
                int c4 = gi & 31;
                float4 v = __ldg((const float4*)(X + ((size_t)(m0 + row) * TSEQ + (t + 1)) * DIN + c4 * 4));
                uint2 pk = { pack_h2(v.x, v.y), pack_h2(v.z, v.w) };
                *(uint2*)&sX[row][c4 * 4] = pk;
            }
        }
        #pragma unroll
        for (int i = 0; i < 2; i++)
            #pragma unroll
            for (int j = 0; j < 2; j++)
                hs[((size_t)erow[i] * TSEQ + t) * HID + eu + 2 * j] = __float2half_rn(hvreg[i][j]);
        if (t < TSEQ - 1) {
            if (tid == 0) { while (vbar[bi] < NGRP) {} }
            __syncthreads();
        }
    }
}

// ---------------- medium GEMM with register double-buffering --------------------------
template <bool TRANS, bool RELU>
__global__ __launch_bounds__(256) void gemm_med(
    const float* __restrict__ A, const float* __restrict__ W,
    const float* __restrict__ bias, float* __restrict__ C,
    int M, int N, int K, int lda, int ldw, int ldc) {
    __shared__ float sA[16][68];
    __shared__ float sW[16][68];
    int m0 = blockIdx.y * 64, n0 = blockIdx.x * 64;
    int tid = threadIdx.x;
    int tx = tid & 15, ty = tid >> 4;
    float acc[4][4] = {};
    float pa[4], pw[4];

    #pragma unroll
    for (int i = 0; i < 4; i++) {
        int idx = tid + i * 256;
        int r = idx >> 4, k = idx & 15;
        int mm = m0 + r, kk = k;
        pa[i] = (mm < M && kk < K) ? A[(size_t)mm * lda + kk] : 0.f;
        int nn = n0 + r;
        float v = 0.f;
        if (TRANS) { if (kk < K && nn < N) v = W[(size_t)kk * ldw + nn]; }
        else       { if (nn < N && kk < K) v = W[(size_t)nn * ldw + kk]; }
        pw[i] = v;
    }
    for (int k0 = 0; k0 < K; k0 += 16) {
        #pragma unroll
        for (int i = 0; i < 4; i++) {
            int idx = tid + i * 256;
            int r = idx >> 4, k = idx & 15;
            sA[k][r] = pa[i];
            sW[k][r] = pw[i];
        }
        __syncthreads();
        if (k0 + 16 < K) {
            #pragma unroll
            for (int i = 0; i < 4; i++) {
                int idx = tid + i * 256;
                int r = idx >> 4, k = idx & 15;
                int mm = m0 + r, kk = k0 + 16 + k;
                pa[i] = (mm < M && kk < K) ? A[(size_t)mm * lda + kk] : 0.f;
                int nn = n0 + r;
                float v = 0.f;
                if (TRANS) { if (kk < K && nn < N) v = W[(size_t)kk * ldw + nn]; }
                else       { if (nn < N && kk < K) v = W[(size_t)nn * ldw + kk]; }
                pw[i] = v;
            }
        }
        #pragma unroll
        for (int k = 0; k < 16; k++) {
            float4 a = *(const float4*)&sA[k][ty * 4];
            float4 b = *(const float4*)&sW[k][tx * 4];
            acc[0][0] += a.x * b.x; acc[0][1] += a.x * b.y; acc[0][2] += a.x * b.z; acc[0][3] += a.x * b.w;
            acc[1][0] += a.y * b.x; acc[1][1] += a.y * b.y; acc[1][2] += a.y * b.z; acc[1][3] += a.y * b.w;
            acc[2][0] += a.z * b.x; acc[2][1] += a.z * b.y; acc[2][2] += a.z * b.z; acc[2][3] += a.z * b.w;
            acc[3][0] += a.w * b.x; acc[3][1] += a.w * b.y; acc[3][2] += a.w * b.z; acc[3][3] += a.w * b.w;
        }
        __syncthreads();
    }
    #pragma unroll
    for (int r = 0; r < 4; r++) {
        int m = m0 + ty * 4 + r;
        if (m >= M) continue;
        #pragma unroll
        for (int cc = 0; cc < 4; cc++) {
            int n = n0 + tx * 4 + cc;
            if (n >= N) continue;
            float v = acc[r][cc];
            if (bias) v += bias[n];
            if (RELU) v = fmaxf(v, 0.f);
            C[(size_t)m * ldc + n] = v;
        }
    }
}

// ---------------- fused attention over fp16 hs (512 threads) -------------------------
__global__ __launch_bounds__(512) void attn_kernel(
    const __half* __restrict__ hs, const float* __restrict__ qk,
    float* __restrict__ hbar) {
    int b = blockIdx.x;
    __shared__ float sc[TSEQ];
    __shared__ float red[256];
    __shared__ float sqk[HID];
    __shared__ float part[2][256];
    int tid = threadIdx.x;
    int lane = tid & 31, w = tid >> 5;   // 16 warps
    if (tid < HID) sqk[tid] = qk[b * HID + tid];
    __syncthreads();
    for (int t = w; t < TSEQ; t += 16) {
        const __half2* hrow = (const __half2*)(hs + ((size_t)b * TSEQ + t) * HID);
        float p = 0.f;
        #pragma unroll
        for (int j = 0; j < 4; j++) {
            int h2i = lane + 32 * j;
            float2 hv = __half22float2(hrow[h2i]);
            p += hv.x * sqk[2 * h2i] + hv.y * sqk[2 * h2i + 1];
        }
        #pragma unroll
        for (int o = 16; o > 0; o >>= 1) p += __shfl_down_sync(0xffffffffu, p, o);
        if (lane == 0) sc[t] = p;
    }
    __syncthreads();
    float scale = 1.0f / sqrtf((float)EDIM);
    float v = (tid < 256) ? sc[tid] * scale : -1e30f;
    if (tid < 256) red[tid] = v;
    __syncthreads();
    for (int s = 128; s > 0; s >>= 1) { if (tid < s) red[tid] = fmaxf(red[tid], red[tid + s]); __syncthreads(); }
    float mx = red[0]; __syncthreads();
    float ev = (tid < 256) ? __expf(v - mx) : 0.f;
    if (tid < 256) red[tid] = ev;
    __syncthreads();
    for (int s = 128; s > 0; s >>= 1) { if (tid < s) red[tid] += red[tid + s]; __syncthreads(); }
    float sum = red[0]; __syncthreads();
    if (tid < 256) sc[tid] = __fdividef(ev, sum);
    __syncthreads();
    // weighted sum: 2-way t-split
    int h = tid & 255, half = tid >> 8;
    const __half* hb = hs + (size_t)b * TSEQ * HID;
    float acc = 0.f;
    for (int t = half * 128; t < (half + 1) * 128; t++)
        acc += sc[t] * __half2float(hb[(size_t)t * HID + h]);
    part[half][h] = acc;
    __syncthreads();
    if (tid < 256) hbar[b * HID + tid] = part[0][tid] + part[1][tid];
}

// ---------------- concat helpers ----------------
__global__ void sf_build(const __half* __restrict__ hs, const float* __restrict__ s,
                         float* __restrict__ sf) {
    int idx = blockIdx.x * blockDim.x + threadIdx.x;
    if (idx >= BATCH * EDIM) return;
    int b = idx / EDIM, j = idx % EDIM;
    sf[idx] = (j < HID) ? __half2float(hs[((size_t)b * TSEQ + (TSEQ - 1)) * HID + j])
                        : s[b * FDIM + (j - HID)];
}
// copies s into merged[:, EDIM:DM] (independent of everything downstream of lstm)
__global__ void scopy(const float* __restrict__ s, float* __restrict__ merged) {
    int idx = blockIdx.x * blockDim.x + threadIdx.x;
    if (idx >= BATCH * FDIM) return;
    int b = idx >> 6, f = idx & 63;
    merged[(size_t)b * NMERG + EDIM + f] = s[idx];
}

// ---------------- 10-qubit VQC; reads merged[:, :40], writes merged[:, DM:DM+10] -----
struct c2f { float x, y; };
__device__ __forceinline__ c2f cmul(c2f a, c2f b) { return { a.x * b.x - a.y * b.y, a.x * b.y + a.y * b.x }; }
__device__ __forceinline__ c2f cadd(c2f a, c2f b) { return { a.x + b.x, a.y + b.y }; }
__device__ __forceinline__ void matmul2(c2f C[2][2], const c2f A[2][2], const c2f B[2][2]) {
    #pragma unroll
    for (int i = 0; i < 2; i++)
        #pragma unroll
        for (int j = 0; j < 2; j++)
            C[i][j] = cadd(cmul(A[i][0], B[0][j]), cmul(A[i][1], B[1][j]));
}
// composite CNOT ring as index map: psi_new[i] = psi_old[g(i)],
// g = f_1 ∘ f_2 ∘ ... ∘ f_10 applied innermost-first (f_10 first).
__device__ __forceinline__ int cnot_ring_gather(int i) {
    int j = i;
    j ^= (j & 1) << 9;                                  // CNOT(9,0): ctrl bit0 -> tgt bit9
    #pragma unroll
    for (int k = 9; k >= 1; k--)                        // CNOT(k-1,k): ctrl bit(10-k) -> tgt bit(9-k)
        j ^= ((j >> (10 - k)) & 1) << (9 - k);
    return j;
}

__global__ __launch_bounds__(512) void vqc_kernel(float* __restrict__ merged,
                                                  const float* __restrict__ qw) {
    int b = blockIdx.x;
    __shared__ c2f psi[1024];
    __shared__ float sang[40];
    __shared__ float wsum[16][10];
    int tid = threadIdx.x;
    int lane = tid & 31, w = tid >> 5;
    const float PI_F = 3.14159265358979323846f;
    psi[tid] = { 0.03125f, 0.f };
    psi[tid + 512] = { 0.03125f, 0.f };
    if (tid < 40) sang[tid] = ftanh(merged[(size_t)b * NMERG + tid]) * PI_F;
    __syncthreads();

    int gidx0 = cnot_ring_gather(tid);
    int gidx1 = cnot_ring_gather(tid + 512);

    for (int layer = 0; layer < 4; layer++) {
        for (int q = 0; q < 10; q++) {
            int idx = layer * 10 + q;
            float a = sang[idx];
            float w0 = qw[idx * 3 + 0], w1 = qw[idx * 3 + 1], w2 = qw[idx * 3 + 2];
            float ch, sh; __sincosf(0.5f * a, &sh, &ch);
            c2f Rx[2][2] = { { {ch, 0.f}, {0.f, -sh} }, { {0.f, -sh}, {ch, 0.f} } };
            c2f Rya[2][2] = { { {ch, 0.f}, {-sh, 0.f} }, { {sh, 0.f}, {ch, 0.f} } };
            c2f T1[2][2]; matmul2(T1, Rya, Rx);
            float c0, s0; __sincosf(0.5f * w0, &s0, &c0);
            c2f Rz0[2][2] = { { {c0, -s0}, {0.f, 0.f} }, { {0.f, 0.f}, {c0, s0} } };
            c2f T2[2][2]; matmul2(T2, Rz0, T1);
            float c1, s1; __sincosf(0.5f * w1, &s1, &c1);
            c2f Ry1[2][2] = { { {c1, 0.f}, {-s1, 0.f} }, { {s1, 0.f}, {c1, 0.f} } };
            c2f T3[2][2]; matmul2(T3, Ry1, T2);
            float c2r, s2r; __sincosf(0.5f * w2, &s2r, &c2r);
            c2f Rz2[2][2] = { { {c2r, -s2r}, {0.f, 0.f} }, { {0.f, 0.f}, {c2r, s2r} } };
            c2f U[2][2]; matmul2(U, Rz2, T3);

            int bq = 9 - q;
            int low = tid & ((1 << bq) - 1);
            int i0 = ((tid >> bq) << (bq + 1)) | low;
            int i1 = i0 | (1 << bq);
            __syncthreads();
            c2f a0 = psi[i0], a1 = psi[i1];
            psi[i0] = cadd(cmul(U[0][0], a0), cmul(U[0][1], a1));
            psi[i1] = cadd(cmul(U[1][0], a0), cmul(U[1][1], a1));
        }
        // CNOT ring as single gather pass
        __syncthreads();
        c2f v0 = psi[gidx0], v1 = psi[gidx1];
        __syncthreads();
        psi[tid] = v0;
        psi[tid + 512] = v1;
    }
    __syncthreads();
    // single-pass measurement of all 10 Z expectations
    c2f p0 = psi[tid], p1 = psi[tid + 512];
    float n0 = p0.x * p0.x + p0.y * p0.y;
    float n1 = p1.x * p1.x + p1.y * p1.y;
    float acc[10];
    #pragma unroll
    for (int k = 0; k < 10; k++) {
        int bp_ = 9 - k;
        float s0v = ((tid >> bp_) & 1) ? -n0 : n0;
        float s1v = (((tid + 512) >> bp_) & 1) ? -n1 : n1;
        acc[k] = s0v + s1v;
        #pragma unroll
        for (int o = 16; o > 0; o >>= 1) acc[k] += __shfl_down_sync(0xffffffffu, acc[k], o);
    }
    if (lane == 0)
        #pragma unroll
        for (int k = 0; k < 10; k++) wsum[w][k] = acc[k];
    __syncthreads();
    if (tid < 10) {
        float a = 0.f;
        #pragma unroll
        for (int ww = 0; ww < 16; ww++) a += wsum[ww][tid];
        merged[(size_t)b * NMERG + DM + tid] = a;
    }
}

// ---------------- host launch ----------------
#define GETSYM(p, sym) do { void* _t = nullptr; cudaGetSymbolAddress(&_t, sym); (p) = (float*)_t; } while (0)

extern "C" void kernel_launch(void* const* d_in, const int* in_sizes, int n_in,
                              void* d_out, int out_size) {
    const float* s          = (const float*)d_in[0];
    const float* lstm_s     = (const float*)d_in[1];
    const float* W_ih       = (const float*)d_in[2];
    const float* W_hh       = (const float*)d_in[3];
    const float* b_ih       = (const float*)d_in[4];
    const float* b_hh       = (const float*)d_in[5];
    const float* proj_W     = (const float*)d_in[6];
    const float* proj_b     = (const float*)d_in[7];
    const float* in_proj_W  = (const float*)d_in[8];
    const float* in_proj_b  = (const float*)d_in[9];
    const float* out_proj_W = (const float*)d_in[10];
    const float* out_proj_b = (const float*)d_in[11];
    const float* qweights   = (const float*)d_in[12];
    const float* W1         = (const float*)d_in[13];
    const float* b1         = (const float*)d_in[14];
    const float* W2         = (const float*)d_in[15];
    const float* b2         = (const float*)d_in[16];
    float* out = (float*)d_out;

    float *sf, *qk, *Mkp, *MA1, *Amat, *P, *cqk;
    float *aconst, *hbar, *merged, *x1;
    __half *hbuf, *hs;
    int* bar;
    { void* _t = nullptr; cudaGetSymbolAddress(&_t, d_hbuf); hbuf = (__half*)_t; }
    { void* _t = nullptr; cudaGetSymbolAddress(&_t, d_hs); hs = (__half*)_t; }
    GETSYM(sf, d_sf);
    GETSYM(qk, d_qk);   GETSYM(Mkp, d_Mkp); GETSYM(MA1, d_MA1);
    GETSYM(Amat, d_Amat); GETSYM(P, d_P);   GETSYM(cqk, d_cqk);
    GETSYM(aconst, d_aconst);
    GETSYM(hbar, d_hbar);
    GETSYM(merged, d_merged); GETSYM(x1, d_x1);
    { void* _t = nullptr; cudaGetSymbolAddress(&_t, d_bar); bar = (int*)_t; }

    cudaMemsetAsync(bar, 0, (16 * TSEQ + 1) * sizeof(int));

    // merged[:, EDIM:DM] = s (depends only on input)
    scopy<<<(BATCH * FDIM + 255) / 256, 256>>>(s, merged);

    // persistent fused LSTM + hidden attention-weight precompose (no permute pass)
    lstm_persist<<<NBLK + NPRE, 256>>>(lstm_s, W_ih, W_hh, b_ih, b_hh, hs, hbuf, bar,
                                       in_proj_W, in_proj_b, proj_W, proj_b,
                                       out_proj_W, out_proj_b,
                                       Mkp, MA1, Amat, P, cqk, aconst);

    // state_full = [h_last, s]; qk = sf @ P + cqk
    sf_build<<<(BATCH * EDIM + 255) / 256, 256>>>(hs, s, sf);
    gemm_med<true, false><<<dim3(4, 8), 256>>>(sf, P, cqk, qk, BATCH, HID, EDIM, EDIM, HID, HID);

    // fused attention over hs
    attn_kernel<<<BATCH, 512>>>(hs, qk, hbar);

    // attn_out written directly into merged[:, :EDIM]
    gemm_med<false, false><<<dim3(5, 8), 256>>>(hbar, Amat, aconst, merged, BATCH, EDIM, HID, HID, HID, NMERG);

    // VQC (writes qfeat into merged[:, DM:])
    vqc_kernel<<<BATCH, 512>>>(merged, qweights);

    // MLP (reads merged directly, lda = NMERG)
    gemm_med<false, true><<<dim3(8, 8), 256>>>(merged, W1, b1, x1, BATCH, NL1, NMERG, NMERG, NMERG, NL1);
    gemm_med<false, false><<<dim3(1, 8), 256>>>(x1, W2, b2, out, BATCH, NACT, NL1, NL1, NL1, NACT);
}